// round 5
// baseline (speedup 1.0000x reference)
#include <cuda_runtime.h>
#include <cstdint>
#include <math.h>

// ---------------------------------------------------------------------------
// GIN_Net forward on GB300 (sm_103a).
// One fused kernel per GIN layer: CSR gather -> GEMM1+bias+ReLU (smem-resident
// intermediate) -> GEMM2+bias+act. GEMMs via mma.sync tf32.
// ---------------------------------------------------------------------------

#define MAX_N 100000
#define MAX_E 1600000
#define HDIM  128
#define PAD   132

__device__ float g_buf0[MAX_N * HDIM];                 // h (layer-1 output)
__device__ float g_wt[3 * 128 * 128 + 64 * 128];       // w1a^T,w1b^T,w2a^T,w2b^T (tf32)
__device__ int   g_adj[MAX_E];
__device__ int   g_rowStart[MAX_N + 1];
__device__ int   g_cursor[MAX_N];
__device__ int   g_deg[MAX_N];

__device__ __forceinline__ float tf32r(float x) {
    float y;
    asm("cvt.rna.tf32.f32 %0, %1;" : "=f"(y) : "f"(x));
    return y;
}

__device__ __forceinline__ void mma_tf32(float d[4], const uint32_t a[4],
                                         uint32_t b0, uint32_t b1) {
    asm volatile(
        "mma.sync.aligned.m16n8k8.row.col.f32.tf32.tf32.f32 "
        "{%0,%1,%2,%3}, {%4,%5,%6,%7}, {%8,%9}, {%0,%1,%2,%3};"
        : "+f"(d[0]), "+f"(d[1]), "+f"(d[2]), "+f"(d[3])
        : "r"(a[0]), "r"(a[1]), "r"(a[2]), "r"(a[3]), "r"(b0), "r"(b1));
}

// ---------------- CSR build -------------------------------------------------
__global__ void hist_kernel(const int* __restrict__ dst, int* __restrict__ deg, int E) {
    int e = blockIdx.x * blockDim.x + threadIdx.x;
    if (e < E) atomicAdd(&deg[dst[e]], 1);
}

__global__ void scan_kernel(const int* __restrict__ deg, int* __restrict__ rowStart,
                            int* __restrict__ cursor, int N) {
    __shared__ int warpSums[32];
    __shared__ int running;
    int tid = threadIdx.x, lane = tid & 31, wid = tid >> 5;
    if (tid == 0) running = 0;
    __syncthreads();
    for (int base = 0; base < N; base += 1024) {
        int i = base + tid;
        int v = (i < N) ? deg[i] : 0;
        int val = v;
#pragma unroll
        for (int off = 1; off < 32; off <<= 1) {
            int t = __shfl_up_sync(0xffffffffu, val, off);
            if (lane >= off) val += t;
        }
        if (lane == 31) warpSums[wid] = val;
        __syncthreads();
        if (wid == 0) {
            int w = warpSums[lane];
#pragma unroll
            for (int off = 1; off < 32; off <<= 1) {
                int t = __shfl_up_sync(0xffffffffu, w, off);
                if (lane >= off) w += t;
            }
            warpSums[lane] = w;
        }
        __syncthreads();
        int warpExcl = (wid == 0) ? 0 : warpSums[wid - 1];
        int excl = running + warpExcl + val - v;
        if (i < N) { rowStart[i] = excl; cursor[i] = excl; }
        __syncthreads();
        if (tid == 0) running += warpSums[31];
        __syncthreads();
    }
    if (tid == 0) rowStart[N] = running;
}

__global__ void fill_kernel(const int* __restrict__ src, const int* __restrict__ dst,
                            int* __restrict__ cursor, int* __restrict__ adj, int E) {
    int e = blockIdx.x * blockDim.x + threadIdx.x;
    if (e < E) {
        int p = atomicAdd(&cursor[dst[e]], 1);
        adj[p] = src[e];
    }
}

// ---------------- weight transposes (one launch) -----------------------------
__global__ void transpose_all(const float* __restrict__ w1a, const float* __restrict__ w1b,
                              const float* __restrict__ w2a, const float* __restrict__ w2b,
                              float* __restrict__ wt) {
    int i = blockIdx.x * blockDim.x + threadIdx.x;
    if (i < 49152) {
        const float* W = (i < 16384) ? w1a : (i < 32768) ? w1b : w2a;
        int li = i & 16383;
        int n = li >> 7, k = li & 127;
        wt[i] = tf32r(W[k * 128 + n]);
    } else if (i < 57344) {
        int li = i - 49152;
        int n = li >> 7, k = li & 127;
        wt[i] = tf32r(w2b[k * 64 + n]);
    }
}

// ---------------- MMA tile loop (256 rows x MOUT cols, 16 warps) ------------
template <int NT>
__device__ __forceinline__ void mma_block(const uint32_t* __restrict__ sAu,
                                          const uint32_t* __restrict__ sWu,
                                          int arow, int bcol0, float (&d)[2][NT][4]) {
#pragma unroll
    for (int mt = 0; mt < 2; mt++)
#pragma unroll
        for (int nt = 0; nt < NT; nt++)
#pragma unroll
            for (int j = 0; j < 4; j++) d[mt][nt][j] = 0.f;

#pragma unroll
    for (int kt = 0; kt < 16; kt++) {
        const int k0 = kt * 8 + (threadIdx.x & 3);
        uint32_t a[2][4];
#pragma unroll
        for (int mt = 0; mt < 2; mt++) {
            int r = arow + mt * 16;
            a[mt][0] = sAu[r * PAD + k0];
            a[mt][1] = sAu[(r + 8) * PAD + k0];
            a[mt][2] = sAu[r * PAD + k0 + 4];
            a[mt][3] = sAu[(r + 8) * PAD + k0 + 4];
        }
#pragma unroll
        for (int nt = 0; nt < NT; nt++) {
            int n = bcol0 + nt * 8 + ((threadIdx.x & 31) >> 2);
            uint32_t b0 = sWu[n * PAD + k0];
            uint32_t b1 = sWu[n * PAD + k0 + 4];
#pragma unroll
            for (int mt = 0; mt < 2; mt++)
                mma_tf32(d[mt][nt], a[mt], b0, b1);
        }
    }
}

// ---------------- fused GIN layer --------------------------------------------
// out = act2(relu(aggr(h) @ W1 + b1) @ W2 + b2)
// aggr(h)[n] = h[n] + sum_{nb} h[nb] via CSR.
// M2: second-GEMM output width (128 or 64). ACT2: 2 = elu, 0 = none.
__device__ __forceinline__ void add4(float4& a, const float4 b) {
    a.x += b.x; a.y += b.y; a.z += b.z; a.w += b.w;
}

template <int M2, int ACT2>
__global__ __launch_bounds__(512, 1)
void fused_layer(const float4* __restrict__ h4,
                 const int* __restrict__ rowStart, const int* __restrict__ adj,
                 const float* __restrict__ Wt1, const float* __restrict__ b1,
                 const float* __restrict__ Wt2, const float* __restrict__ b2,
                 float* __restrict__ Cout, int N)
{
    constexpr int NT1 = 8;        // 128/16
    constexpr int NT2 = M2 / 16;  // 8 or 4

    extern __shared__ float smem[];
    float* sA  = smem;                 // [256][PAD] : A tile, then intermediate
    float* sW  = smem + 256 * PAD;     // [128][PAD] : W1, then W2
    float* sB1 = sW + 128 * PAD;       // [128]
    float* sB2 = sB1 + 128;            // [M2]

    const int tid  = threadIdx.x;
    const int wid  = tid >> 5;
    const int lane = tid & 31;
    const int row0 = blockIdx.x * 256;

    // stage W1 (tf32-rounded already)
    for (int i = tid; i < 128 * 32; i += 512) {
        int n = i >> 5, k4 = i & 31;
        *(float4*)(sW + n * PAD + k4 * 4) = ((const float4*)Wt1)[i];
    }
    if (tid < 128) sB1[tid] = b1[tid];
    if (tid < M2)  sB2[tid] = b2[tid];

    // gather A tile: warp w handles rows [w*16, w*16+16)
    for (int rr = 0; rr < 16; rr++) {
        int r  = wid * 16 + rr;
        int gr = row0 + r;
        float4 acc = make_float4(0.f, 0.f, 0.f, 0.f);
        if (gr < N) {
            acc = h4[(size_t)gr * 32 + lane];          // self term
            int s = __ldg(rowStart + gr);
            int e = __ldg(rowStart + gr + 1);
            int j = s;
            for (; j + 3 < e; j += 4) {
                int n0 = __ldg(adj + j),     n1 = __ldg(adj + j + 1);
                int n2 = __ldg(adj + j + 2), n3 = __ldg(adj + j + 3);
                float4 v0 = h4[(size_t)n0 * 32 + lane];
                float4 v1 = h4[(size_t)n1 * 32 + lane];
                float4 v2 = h4[(size_t)n2 * 32 + lane];
                float4 v3 = h4[(size_t)n3 * 32 + lane];
                add4(acc, v0); add4(acc, v1); add4(acc, v2); add4(acc, v3);
            }
            for (; j < e; j++)
                add4(acc, h4[(size_t)__ldg(adj + j) * 32 + lane]);
        }
        acc.x = tf32r(acc.x); acc.y = tf32r(acc.y);
        acc.z = tf32r(acc.z); acc.w = tf32r(acc.w);
        *(float4*)(sA + r * PAD + lane * 4) = acc;
    }
    __syncthreads();

    const int warp_n = wid >> 3;      // 0..1
    const int warp_m = wid & 7;       // 0..7
    const int gid    = lane >> 2;     // 0..7
    const int tig    = lane & 3;      // 0..3
    const int arow   = warp_m * 32 + gid;

    const uint32_t* sAu = (const uint32_t*)sA;
    const uint32_t* sWu = (const uint32_t*)sW;

    // ---- GEMM1: 256x128, bias + relu ----
    float d1[2][NT1][4];
    mma_block<NT1>(sAu, sWu, arow, warp_n * 64, d1);

    // bias + relu + tf32 round into registers
#pragma unroll
    for (int mt = 0; mt < 2; mt++)
#pragma unroll
        for (int nt = 0; nt < NT1; nt++)
#pragma unroll
            for (int half = 0; half < 2; half++) {
                int col = warp_n * 64 + nt * 8 + tig * 2;
                float v0 = fmaxf(d1[mt][nt][half * 2 + 0] + sB1[col], 0.f);
                float v1 = fmaxf(d1[mt][nt][half * 2 + 1] + sB1[col + 1], 0.f);
                d1[mt][nt][half * 2 + 0] = tf32r(v0);
                d1[mt][nt][half * 2 + 1] = tf32r(v1);
            }
    __syncthreads();   // all MMA1 smem reads complete

    // write intermediate over sA; stage W2 over sW
#pragma unroll
    for (int mt = 0; mt < 2; mt++) {
        int rb = warp_m * 32 + mt * 16 + gid;
#pragma unroll
        for (int half = 0; half < 2; half++) {
            int r = rb + half * 8;
#pragma unroll
            for (int nt = 0; nt < NT1; nt++) {
                int col = warp_n * 64 + nt * 8 + tig * 2;
                *(float2*)(sA + r * PAD + col) =
                    make_float2(d1[mt][nt][half * 2], d1[mt][nt][half * 2 + 1]);
            }
        }
    }
    for (int i = tid; i < M2 * 32; i += 512) {
        int n = i >> 5, k4 = i & 31;
        *(float4*)(sW + n * PAD + k4 * 4) = ((const float4*)Wt2)[i];
    }
    __syncthreads();

    // ---- GEMM2: 256xM2, bias + act2, store to global ----
    float d2[2][NT2][4];
    mma_block<NT2>(sAu, sWu, arow, warp_n * (M2 / 2), d2);

#pragma unroll
    for (int mt = 0; mt < 2; mt++) {
        int rbase = row0 + warp_m * 32 + mt * 16 + gid;
#pragma unroll
        for (int half = 0; half < 2; half++) {
            int r = rbase + half * 8;
            if (r < N) {
#pragma unroll
                for (int nt = 0; nt < NT2; nt++) {
                    int col = warp_n * (M2 / 2) + nt * 8 + tig * 2;
                    float v0 = d2[mt][nt][half * 2 + 0] + sB2[col];
                    float v1 = d2[mt][nt][half * 2 + 1] + sB2[col + 1];
                    if (ACT2 == 2) {
                        v0 = (v0 > 0.f) ? v0 : expm1f(v0);
                        v1 = (v1 > 0.f) ? v1 : expm1f(v1);
                    }
                    *(float2*)(Cout + (size_t)r * M2 + col) = make_float2(v0, v1);
                }
            }
        }
    }
}

// ---------------------------------------------------------------------------
extern "C" void kernel_launch(void* const* d_in, const int* in_sizes, int n_in,
                              void* d_out, int out_size) {
    const float* x   = (const float*)d_in[0];
    const float* Q   = (const float*)d_in[1];
    const float* w1a = (const float*)d_in[2];
    const float* b1a = (const float*)d_in[3];
    const float* w1b = (const float*)d_in[4];
    const float* b1b = (const float*)d_in[5];
    const float* w2a = (const float*)d_in[6];
    const float* b2a = (const float*)d_in[7];
    const float* w2b = (const float*)d_in[8];
    const float* b2b = (const float*)d_in[9];
    const int*   ei  = (const int*)d_in[10];

    int N = in_sizes[0] / 128;
    int E = in_sizes[10] / 2;
    int C = in_sizes[9];
    int qn = in_sizes[1];

    float* out = (float*)d_out;
    float *buf0, *wt;
    int *adj, *rowStart, *cursor, *deg;
    cudaGetSymbolAddress((void**)&buf0, g_buf0);
    cudaGetSymbolAddress((void**)&wt,   g_wt);
    cudaGetSymbolAddress((void**)&adj,      g_adj);
    cudaGetSymbolAddress((void**)&rowStart, g_rowStart);
    cudaGetSymbolAddress((void**)&cursor,   g_cursor);
    cudaGetSymbolAddress((void**)&deg,      g_deg);

    float* wt1a = wt;
    float* wt1b = wt + 16384;
    float* wt2a = wt + 32768;
    float* wt2b = wt + 49152;

    const int* srcI = ei;
    const int* dstI = ei + E;

    const int smemL = (256 * PAD + 128 * PAD + 128 + 128) * (int)sizeof(float);  // ~203 KB
    cudaFuncSetAttribute(fused_layer<128, 2>, cudaFuncAttributeMaxDynamicSharedMemorySize, smemL);
    cudaFuncSetAttribute(fused_layer<64, 0>,  cudaFuncAttributeMaxDynamicSharedMemorySize, smemL);

    // Q pass-through
    cudaMemcpyAsync(out + (size_t)N * C, Q, (size_t)qn * sizeof(float),
                    cudaMemcpyDeviceToDevice, 0);

    // CSR build
    cudaMemsetAsync(deg, 0, N * sizeof(int), 0);
    hist_kernel<<<(E + 255) / 256, 256>>>(dstI, deg, E);
    scan_kernel<<<1, 1024>>>(deg, rowStart, cursor, N);
    fill_kernel<<<(E + 255) / 256, 256>>>(srcI, dstI, cursor, adj, E);

    // weight transposes
    transpose_all<<<(57344 + 255) / 256, 256>>>(w1a, w1b, w2a, w2b, wt);

    int blocks = (N + 255) / 256;

    // layer 1: h = elu(relu(aggr(x) @ w1a + b1a) @ w1b + b1b)
    fused_layer<128, 2><<<blocks, 512, smemL>>>(
        (const float4*)x, rowStart, adj, wt1a, b1a, wt1b, b1b, buf0, N);

    // layer 2: out = relu(aggr(h) @ w2a + b2a) @ w2b + b2b
    fused_layer<64, 0><<<blocks, 512, smemL>>>(
        (const float4*)buf0, rowStart, adj, wt2a, b2a, wt2b, b2b, out, N);
}

// round 6
// speedup vs baseline: 1.2175x; 1.2175x over previous
#include <cuda_runtime.h>
#include <cstdint>
#include <math.h>

// ---------------------------------------------------------------------------
// GIN_Net forward on GB300 (sm_103a).
// Per layer: high-occupancy CSR gather kernel (with Q-copy blocks folded in),
// then a fused MLP kernel (GEMM1+bias+relu -> smem -> GEMM2+bias+act) on
// mma.sync tf32.
// ---------------------------------------------------------------------------

#define MAX_N 100000
#define MAX_E 1600000
#define HDIM  128
#define PAD   132

__device__ float g_buf0[MAX_N * HDIM];
__device__ float g_buf1[MAX_N * HDIM];
__device__ float g_wt[3 * 128 * 128 + 64 * 128];   // w1a^T,w1b^T,w2a^T,w2b^T (tf32)
__device__ int   g_adj[MAX_E];
__device__ int   g_rowStart[MAX_N + 1];
__device__ int   g_cursor[MAX_N];
__device__ int   g_deg[MAX_N];

__device__ __forceinline__ float tf32r(float x) {
    float y;
    asm("cvt.rna.tf32.f32 %0, %1;" : "=f"(y) : "f"(x));
    return y;
}

__device__ __forceinline__ void mma_tf32(float d[4], const uint32_t a[4],
                                         uint32_t b0, uint32_t b1) {
    asm volatile(
        "mma.sync.aligned.m16n8k8.row.col.f32.tf32.tf32.f32 "
        "{%0,%1,%2,%3}, {%4,%5,%6,%7}, {%8,%9}, {%0,%1,%2,%3};"
        : "+f"(d[0]), "+f"(d[1]), "+f"(d[2]), "+f"(d[3])
        : "r"(a[0]), "r"(a[1]), "r"(a[2]), "r"(a[3]), "r"(b0), "r"(b1));
}

// ---------------- CSR build -------------------------------------------------
__global__ void hist_kernel(const int* __restrict__ dst, int* __restrict__ deg, int E) {
    int e = blockIdx.x * blockDim.x + threadIdx.x;
    if (e < E) atomicAdd(&deg[dst[e]], 1);
}

__global__ void scan_kernel(const int* __restrict__ deg, int* __restrict__ rowStart,
                            int* __restrict__ cursor, int N) {
    __shared__ int warpSums[32];
    __shared__ int running;
    int tid = threadIdx.x, lane = tid & 31, wid = tid >> 5;
    if (tid == 0) running = 0;
    __syncthreads();
    for (int base = 0; base < N; base += 1024) {
        int i = base + tid;
        int v = (i < N) ? deg[i] : 0;
        int val = v;
#pragma unroll
        for (int off = 1; off < 32; off <<= 1) {
            int t = __shfl_up_sync(0xffffffffu, val, off);
            if (lane >= off) val += t;
        }
        if (lane == 31) warpSums[wid] = val;
        __syncthreads();
        if (wid == 0) {
            int w = warpSums[lane];
#pragma unroll
            for (int off = 1; off < 32; off <<= 1) {
                int t = __shfl_up_sync(0xffffffffu, w, off);
                if (lane >= off) w += t;
            }
            warpSums[lane] = w;
        }
        __syncthreads();
        int warpExcl = (wid == 0) ? 0 : warpSums[wid - 1];
        int excl = running + warpExcl + val - v;
        if (i < N) { rowStart[i] = excl; cursor[i] = excl; }
        __syncthreads();
        if (tid == 0) running += warpSums[31];
        __syncthreads();
    }
    if (tid == 0) rowStart[N] = running;
}

__global__ void fill_kernel(const int* __restrict__ src, const int* __restrict__ dst,
                            int* __restrict__ cursor, int* __restrict__ adj, int E) {
    int e = blockIdx.x * blockDim.x + threadIdx.x;
    if (e < E) {
        int p = atomicAdd(&cursor[dst[e]], 1);
        adj[p] = src[e];
    }
}

// ---------------- weight transposes -----------------------------------------
__global__ void transpose_all(const float* __restrict__ w1a, const float* __restrict__ w1b,
                              const float* __restrict__ w2a, const float* __restrict__ w2b,
                              float* __restrict__ wt) {
    int i = blockIdx.x * blockDim.x + threadIdx.x;
    if (i < 49152) {
        const float* W = (i < 16384) ? w1a : (i < 32768) ? w1b : w2a;
        int li = i & 16383;
        int n = li >> 7, k = li & 127;
        wt[i] = tf32r(W[k * 128 + n]);
    } else if (i < 57344) {
        int li = i - 49152;
        int n = li >> 7, k = li & 127;
        wt[i] = tf32r(w2b[k * 64 + n]);
    }
}

// ---------------- CSR gather + folded Q copy --------------------------------
// blocks [0, gatBlocks): out[n] = h[n] + sum_{nb} h[nb]   (one warp per row)
// blocks [gatBlocks, gridDim): grid-stride copy of a Q chunk (overlaps copy
// bandwidth with gather's L2-bound phase)
__device__ __forceinline__ void add4(float4& a, const float4 b) {
    a.x += b.x; a.y += b.y; a.z += b.z; a.w += b.w;
}

__global__ void gather_copy_kernel(const float4* __restrict__ h4,
                                   const int* __restrict__ rowStart,
                                   const int* __restrict__ adj,
                                   float4* __restrict__ out4, int N, int gatBlocks,
                                   const float4* __restrict__ qsrc,
                                   float4* __restrict__ qdst, int qcount4) {
    if ((int)blockIdx.x >= gatBlocks) {
        long i = (long)(blockIdx.x - gatBlocks) * blockDim.x + threadIdx.x;
        long stride = (long)(gridDim.x - gatBlocks) * blockDim.x;
        for (; i < qcount4; i += stride) qdst[i] = qsrc[i];
        return;
    }
    int warp = (blockIdx.x * blockDim.x + threadIdx.x) >> 5;
    int lane = threadIdx.x & 31;
    if (warp >= N) return;
    int s = __ldg(rowStart + warp);
    int e = __ldg(rowStart + warp + 1);
    float4 acc = h4[(size_t)warp * 32 + lane];   // self term
    int j = s;
    for (; j + 3 < e; j += 4) {
        int n0 = __ldg(adj + j),     n1 = __ldg(adj + j + 1);
        int n2 = __ldg(adj + j + 2), n3 = __ldg(adj + j + 3);
        float4 v0 = h4[(size_t)n0 * 32 + lane];
        float4 v1 = h4[(size_t)n1 * 32 + lane];
        float4 v2 = h4[(size_t)n2 * 32 + lane];
        float4 v3 = h4[(size_t)n3 * 32 + lane];
        add4(acc, v0); add4(acc, v1); add4(acc, v2); add4(acc, v3);
    }
    for (; j < e; j++)
        add4(acc, h4[(size_t)__ldg(adj + j) * 32 + lane]);
    out4[(size_t)warp * 32 + lane] = acc;
}

// ---------------- MMA tile loop (256 rows x cols, 16 warps) -----------------
template <int NT>
__device__ __forceinline__ void mma_block(const uint32_t* __restrict__ sAu,
                                          const uint32_t* __restrict__ sWu,
                                          int arow, int bcol0, float (&d)[2][NT][4]) {
#pragma unroll
    for (int mt = 0; mt < 2; mt++)
#pragma unroll
        for (int nt = 0; nt < NT; nt++)
#pragma unroll
            for (int j = 0; j < 4; j++) d[mt][nt][j] = 0.f;

#pragma unroll
    for (int kt = 0; kt < 16; kt++) {
        const int k0 = kt * 8 + (threadIdx.x & 3);
        uint32_t a[2][4];
#pragma unroll
        for (int mt = 0; mt < 2; mt++) {
            int r = arow + mt * 16;
            a[mt][0] = sAu[r * PAD + k0];
            a[mt][1] = sAu[(r + 8) * PAD + k0];
            a[mt][2] = sAu[r * PAD + k0 + 4];
            a[mt][3] = sAu[(r + 8) * PAD + k0 + 4];
        }
#pragma unroll
        for (int nt = 0; nt < NT; nt++) {
            int n = bcol0 + nt * 8 + ((threadIdx.x & 31) >> 2);
            uint32_t b0 = sWu[n * PAD + k0];
            uint32_t b1 = sWu[n * PAD + k0 + 4];
#pragma unroll
            for (int mt = 0; mt < 2; mt++)
                mma_tf32(d[mt][nt], a[mt], b0, b1);
        }
    }
}

// ---------------- fused 2-layer MLP ------------------------------------------
// Cout = act2(relu(A @ W1 + b1) @ W2 + b2); A read from global (pre-aggregated)
// M2: output width; ACT2: 2=elu, 0=none.
template <int M2, int ACT2>
__global__ __launch_bounds__(512, 1)
void mlp_fused(const float* __restrict__ A,
               const float* __restrict__ Wt1, const float* __restrict__ b1,
               const float* __restrict__ Wt2, const float* __restrict__ b2,
               float* __restrict__ Cout, int N)
{
    constexpr int NT1 = 8;
    constexpr int NT2 = M2 / 16;

    extern __shared__ float smem[];
    float* sA  = smem;                 // [256][PAD] : A tile, then intermediate
    float* sW  = smem + 256 * PAD;     // [128][PAD] : W1, then W2
    float* sB1 = sW + 128 * PAD;
    float* sB2 = sB1 + 128;

    const int tid  = threadIdx.x;
    const int row0 = blockIdx.x * 256;

    for (int i = tid; i < 128 * 32; i += 512) {
        int n = i >> 5, k4 = i & 31;
        *(float4*)(sW + n * PAD + k4 * 4) = ((const float4*)Wt1)[i];
    }
    if (tid < 128) sB1[tid] = b1[tid];
    if (tid < M2)  sB2[tid] = b2[tid];

    for (int i = tid; i < 256 * 32; i += 512) {
        int r = i >> 5, k4 = i & 31;
        float4 v = make_float4(0.f, 0.f, 0.f, 0.f);
        if (row0 + r < N) v = ((const float4*)A)[(size_t)(row0 + r) * 32 + k4];
        v.x = tf32r(v.x); v.y = tf32r(v.y); v.z = tf32r(v.z); v.w = tf32r(v.w);
        *(float4*)(sA + r * PAD + k4 * 4) = v;
    }
    __syncthreads();

    const int wid    = tid >> 5;
    const int lane   = tid & 31;
    const int warp_n = wid >> 3;
    const int warp_m = wid & 7;
    const int gid    = lane >> 2;
    const int tig    = lane & 3;
    const int arow   = warp_m * 32 + gid;

    const uint32_t* sAu = (const uint32_t*)sA;
    const uint32_t* sWu = (const uint32_t*)sW;

    // GEMM1 + bias + relu (tf32-rounded, kept in registers)
    float d1[2][NT1][4];
    mma_block<NT1>(sAu, sWu, arow, warp_n * 64, d1);
#pragma unroll
    for (int mt = 0; mt < 2; mt++)
#pragma unroll
        for (int nt = 0; nt < NT1; nt++)
#pragma unroll
            for (int half = 0; half < 2; half++) {
                int col = warp_n * 64 + nt * 8 + tig * 2;
                float v0 = fmaxf(d1[mt][nt][half * 2 + 0] + sB1[col], 0.f);
                float v1 = fmaxf(d1[mt][nt][half * 2 + 1] + sB1[col + 1], 0.f);
                d1[mt][nt][half * 2 + 0] = tf32r(v0);
                d1[mt][nt][half * 2 + 1] = tf32r(v1);
            }
    __syncthreads();

    // intermediate -> sA; W2 -> sW
#pragma unroll
    for (int mt = 0; mt < 2; mt++) {
        int rb = warp_m * 32 + mt * 16 + gid;
#pragma unroll
        for (int half = 0; half < 2; half++) {
            int r = rb + half * 8;
#pragma unroll
            for (int nt = 0; nt < NT1; nt++) {
                int col = warp_n * 64 + nt * 8 + tig * 2;
                *(float2*)(sA + r * PAD + col) =
                    make_float2(d1[mt][nt][half * 2], d1[mt][nt][half * 2 + 1]);
            }
        }
    }
    for (int i = tid; i < M2 * 32; i += 512) {
        int n = i >> 5, k4 = i & 31;
        *(float4*)(sW + n * PAD + k4 * 4) = ((const float4*)Wt2)[i];
    }
    __syncthreads();

    // GEMM2 + bias + act2 -> global
    float d2[2][NT2][4];
    mma_block<NT2>(sAu, sWu, arow, warp_n * (M2 / 2), d2);
#pragma unroll
    for (int mt = 0; mt < 2; mt++) {
        int rbase = row0 + warp_m * 32 + mt * 16 + gid;
#pragma unroll
        for (int half = 0; half < 2; half++) {
            int r = rbase + half * 8;
            if (r < N) {
#pragma unroll
                for (int nt = 0; nt < NT2; nt++) {
                    int col = warp_n * (M2 / 2) + nt * 8 + tig * 2;
                    float v0 = d2[mt][nt][half * 2 + 0] + sB2[col];
                    float v1 = d2[mt][nt][half * 2 + 1] + sB2[col + 1];
                    if (ACT2 == 2) {
                        v0 = (v0 > 0.f) ? v0 : expm1f(v0);
                        v1 = (v1 > 0.f) ? v1 : expm1f(v1);
                    }
                    *(float2*)(Cout + (size_t)r * M2 + col) = make_float2(v0, v1);
                }
            }
        }
    }
}

// ---------------------------------------------------------------------------
extern "C" void kernel_launch(void* const* d_in, const int* in_sizes, int n_in,
                              void* d_out, int out_size) {
    const float* x   = (const float*)d_in[0];
    const float* Q   = (const float*)d_in[1];
    const float* w1a = (const float*)d_in[2];
    const float* b1a = (const float*)d_in[3];
    const float* w1b = (const float*)d_in[4];
    const float* b1b = (const float*)d_in[5];
    const float* w2a = (const float*)d_in[6];
    const float* b2a = (const float*)d_in[7];
    const float* w2b = (const float*)d_in[8];
    const float* b2b = (const float*)d_in[9];
    const int*   ei  = (const int*)d_in[10];

    int N = in_sizes[0] / 128;
    int E = in_sizes[10] / 2;
    int C = in_sizes[9];
    int qn = in_sizes[1];

    float* out = (float*)d_out;
    float *buf0, *buf1, *wt;
    int *adj, *rowStart, *cursor, *deg;
    cudaGetSymbolAddress((void**)&buf0, g_buf0);
    cudaGetSymbolAddress((void**)&buf1, g_buf1);
    cudaGetSymbolAddress((void**)&wt,   g_wt);
    cudaGetSymbolAddress((void**)&adj,      g_adj);
    cudaGetSymbolAddress((void**)&rowStart, g_rowStart);
    cudaGetSymbolAddress((void**)&cursor,   g_cursor);
    cudaGetSymbolAddress((void**)&deg,      g_deg);

    float* wt1a = wt;
    float* wt1b = wt + 16384;
    float* wt2a = wt + 32768;
    float* wt2b = wt + 49152;

    const int* srcI = ei;
    const int* dstI = ei + E;

    const int smemL = (256 * PAD + 128 * PAD + 128 + 128) * (int)sizeof(float);  // ~203 KB
    cudaFuncSetAttribute(mlp_fused<128, 2>, cudaFuncAttributeMaxDynamicSharedMemorySize, smemL);
    cudaFuncSetAttribute(mlp_fused<64, 0>,  cudaFuncAttributeMaxDynamicSharedMemorySize, smemL);

    // CSR build
    cudaMemsetAsync(deg, 0, N * sizeof(int), 0);
    hist_kernel<<<(E + 255) / 256, 256>>>(dstI, deg, E);
    scan_kernel<<<1, 1024>>>(deg, rowStart, cursor, N);
    fill_kernel<<<(E + 255) / 256, 256>>>(srcI, dstI, cursor, adj, E);

    // weight transposes
    transpose_all<<<(57344 + 255) / 256, 256>>>(w1a, w1b, w2a, w2b, wt);

    // Q copy split across the two gather launches
    int q4total = qn / 4;
    int q4a = q4total / 2;
    int q4b = q4total - q4a;
    const float4* q4src = (const float4*)Q;
    float4* q4dst = (float4*)(out + (size_t)N * C);

    int gatBlocks  = (N * 32 + 255) / 256;
    int copyBlocks = 1500;
    int mlpBlocks  = (N + 255) / 256;

    // layer 1
    gather_copy_kernel<<<gatBlocks + copyBlocks, 256>>>(
        (const float4*)x, rowStart, adj, (float4*)buf0, N, gatBlocks,
        q4src, q4dst, q4a);
    mlp_fused<128, 2><<<mlpBlocks, 512, smemL>>>(buf0, wt1a, b1a, wt1b, b1b, buf1, N);

    // layer 2 (h in buf1)
    gather_copy_kernel<<<gatBlocks + copyBlocks, 256>>>(
        (const float4*)buf1, rowStart, adj, (float4*)buf0, N, gatBlocks,
        q4src + q4a, q4dst + q4a, q4b);
    mlp_fused<64, 0><<<mlpBlocks, 512, smemL>>>(buf0, wt2a, b2a, wt2b, b2b, out, N);
}

// round 11
// speedup vs baseline: 1.2523x; 1.0286x over previous
#include <cuda_runtime.h>
#include <cstdint>
#include <math.h>

// ---------------------------------------------------------------------------
// GIN_Net forward on GB300 (sm_103a).
// Per layer: high-occupancy CSR gather, then fused MLP (GEMM1+relu -> smem ->
// GEMM2+act) on mma.sync tf32. Q pass-through copy is spread as extra block
// ranges across ALL launches (build + gathers) to hide it in idle DRAM time.
// ---------------------------------------------------------------------------

#define MAX_N 100000
#define MAX_E 1600000
#define HDIM  128
#define PAD   132

__device__ float g_buf0[MAX_N * HDIM];
__device__ float g_buf1[MAX_N * HDIM];
__device__ float g_wt[3 * 128 * 128 + 64 * 128];   // w1a^T,w1b^T,w2a^T,w2b^T (tf32)
__device__ int   g_adj[MAX_E];
__device__ __align__(16) int g_rowStart[MAX_N + 1];
__device__ __align__(16) int g_cursor[MAX_N];
__device__ __align__(16) int g_deg[MAX_N];

__device__ __forceinline__ float tf32r(float x) {
    float y;
    asm("cvt.rna.tf32.f32 %0, %1;" : "=f"(y) : "f"(x));
    return y;
}

__device__ __forceinline__ void mma_tf32(float d[4], const uint32_t a[4],
                                         uint32_t b0, uint32_t b1) {
    asm volatile(
        "mma.sync.aligned.m16n8k8.row.col.f32.tf32.tf32.f32 "
        "{%0,%1,%2,%3}, {%4,%5,%6,%7}, {%8,%9}, {%0,%1,%2,%3};"
        : "+f"(d[0]), "+f"(d[1]), "+f"(d[2]), "+f"(d[3])
        : "r"(a[0]), "r"(a[1]), "r"(a[2]), "r"(a[3]), "r"(b0), "r"(b1));
}

// grid-stride float4 copy helper used by the folded copy block-ranges
__device__ __forceinline__ void copy_range(int blk0,
                                           const float4* __restrict__ qsrc,
                                           float4* __restrict__ qdst, int qcount4) {
    long i = (long)(blockIdx.x - blk0) * blockDim.x + threadIdx.x;
    long stride = (long)(gridDim.x - blk0) * blockDim.x;
    for (; i < qcount4; i += stride) qdst[i] = qsrc[i];
}

// ---------------- build: hist + weight transpose + copy ----------------------
__global__ void hist_tp_copy_kernel(const int* __restrict__ dst, int* __restrict__ deg, int E,
                                    int histBlocks,
                                    const float* __restrict__ w1a, const float* __restrict__ w1b,
                                    const float* __restrict__ w2a, const float* __restrict__ w2b,
                                    float* __restrict__ wt, int tpBlocks,
                                    const float4* __restrict__ qsrc, float4* __restrict__ qdst,
                                    int qcount4) {
    int b = blockIdx.x;
    if (b < histBlocks) {
        int e = b * blockDim.x + threadIdx.x;
        if (e < E) atomicAdd(&deg[dst[e]], 1);
        return;
    }
    if (b < histBlocks + tpBlocks) {
        int i = (b - histBlocks) * blockDim.x + threadIdx.x;
        if (i < 49152) {
            const float* W = (i < 16384) ? w1a : (i < 32768) ? w1b : w2a;
            int li = i & 16383;
            int n = li >> 7, k = li & 127;
            wt[i] = tf32r(W[k * 128 + n]);
        } else if (i < 57344) {
            int li = i - 49152;
            int n = li >> 7, k = li & 127;
            wt[i] = tf32r(w2b[k * 64 + n]);
        }
        return;
    }
    copy_range(histBlocks + tpBlocks, qsrc, qdst, qcount4);
}

// ---------------- build: scan (block 0) + copy (rest) ------------------------
// block 0: exclusive prefix sum of deg -> rowStart, cursor (4 elems/thread).
__global__ void scan_copy_kernel(const int* __restrict__ deg, int* __restrict__ rowStart,
                                 int* __restrict__ cursor, int N,
                                 const float4* __restrict__ qsrc, float4* __restrict__ qdst,
                                 int qcount4) {
    if (blockIdx.x != 0) { copy_range(1, qsrc, qdst, qcount4); return; }

    __shared__ int warpSums[32];
    __shared__ int running;
    int tid = threadIdx.x, lane = tid & 31, wid = tid >> 5;
    if (tid == 0) running = 0;
    __syncthreads();
    for (int base = 0; base < N; base += 4096) {
        int i0 = base + tid * 4;
        int v0 = 0, v1 = 0, v2 = 0, v3 = 0;
        if (i0 + 3 < N) {
            int4 t = *(const int4*)(deg + i0);
            v0 = t.x; v1 = t.y; v2 = t.z; v3 = t.w;
        } else {
            if (i0 + 0 < N) v0 = deg[i0 + 0];
            if (i0 + 1 < N) v1 = deg[i0 + 1];
            if (i0 + 2 < N) v2 = deg[i0 + 2];
            if (i0 + 3 < N) v3 = deg[i0 + 3];
        }
        int s = v0 + v1 + v2 + v3;
        int val = s;
#pragma unroll
        for (int off = 1; off < 32; off <<= 1) {
            int t = __shfl_up_sync(0xffffffffu, val, off);
            if (lane >= off) val += t;
        }
        if (lane == 31) warpSums[wid] = val;
        __syncthreads();
        if (wid == 0) {
            int w = warpSums[lane];
#pragma unroll
            for (int off = 1; off < 32; off <<= 1) {
                int t = __shfl_up_sync(0xffffffffu, w, off);
                if (lane >= off) w += t;
            }
            warpSums[lane] = w;
        }
        __syncthreads();
        int excl = running + ((wid == 0) ? 0 : warpSums[wid - 1]) + val - s;
        int r = excl;
        if (i0 + 0 < N) { rowStart[i0 + 0] = r; cursor[i0 + 0] = r; r += v0; }
        if (i0 + 1 < N) { rowStart[i0 + 1] = r; cursor[i0 + 1] = r; r += v1; }
        if (i0 + 2 < N) { rowStart[i0 + 2] = r; cursor[i0 + 2] = r; r += v2; }
        if (i0 + 3 < N) { rowStart[i0 + 3] = r; cursor[i0 + 3] = r; r += v3; }
        __syncthreads();
        if (tid == 0) running += warpSums[31];
        __syncthreads();
    }
    if (tid == 0) rowStart[N] = running;
}

// ---------------- build: fill + copy -----------------------------------------
__global__ void fill_copy_kernel(const int* __restrict__ src, const int* __restrict__ dst,
                                 int* __restrict__ cursor, int* __restrict__ adj, int E,
                                 int fillBlocks,
                                 const float4* __restrict__ qsrc, float4* __restrict__ qdst,
                                 int qcount4) {
    if ((int)blockIdx.x >= fillBlocks) { copy_range(fillBlocks, qsrc, qdst, qcount4); return; }
    int e = blockIdx.x * blockDim.x + threadIdx.x;
    if (e < E) {
        int p = atomicAdd(&cursor[dst[e]], 1);
        adj[p] = src[e];
    }
}

// ---------------- CSR gather + folded Q copy ---------------------------------
__device__ __forceinline__ void add4(float4& a, const float4 b) {
    a.x += b.x; a.y += b.y; a.z += b.z; a.w += b.w;
}

__global__ void gather_copy_kernel(const float4* __restrict__ h4,
                                   const int* __restrict__ rowStart,
                                   const int* __restrict__ adj,
                                   float4* __restrict__ out4, int N, int gatBlocks,
                                   const float4* __restrict__ qsrc,
                                   float4* __restrict__ qdst, int qcount4) {
    if ((int)blockIdx.x >= gatBlocks) { copy_range(gatBlocks, qsrc, qdst, qcount4); return; }
    int warp = (blockIdx.x * blockDim.x + threadIdx.x) >> 5;
    int lane = threadIdx.x & 31;
    if (warp >= N) return;
    int s = __ldg(rowStart + warp);
    int e = __ldg(rowStart + warp + 1);
    float4 acc = h4[(size_t)warp * 32 + lane];   // self term
    int j = s;
    for (; j + 3 < e; j += 4) {
        int n0 = __ldg(adj + j),     n1 = __ldg(adj + j + 1);
        int n2 = __ldg(adj + j + 2), n3 = __ldg(adj + j + 3);
        float4 v0 = h4[(size_t)n0 * 32 + lane];
        float4 v1 = h4[(size_t)n1 * 32 + lane];
        float4 v2 = h4[(size_t)n2 * 32 + lane];
        float4 v3 = h4[(size_t)n3 * 32 + lane];
        add4(acc, v0); add4(acc, v1); add4(acc, v2); add4(acc, v3);
    }
    for (; j < e; j++)
        add4(acc, h4[(size_t)__ldg(adj + j) * 32 + lane]);
    out4[(size_t)warp * 32 + lane] = acc;
}

// ---------------- MMA tile loop (256 rows x cols, 16 warps) -----------------
template <int NT>
__device__ __forceinline__ void mma_block(const uint32_t* __restrict__ sAu,
                                          const uint32_t* __restrict__ sWu,
                                          int arow, int bcol0, float (&d)[2][NT][4]) {
#pragma unroll
    for (int mt = 0; mt < 2; mt++)
#pragma unroll
        for (int nt = 0; nt < NT; nt++)
#pragma unroll
            for (int j = 0; j < 4; j++) d[mt][nt][j] = 0.f;

#pragma unroll
    for (int kt = 0; kt < 16; kt++) {
        const int k0 = kt * 8 + (threadIdx.x & 3);
        uint32_t a[2][4];
#pragma unroll
        for (int mt = 0; mt < 2; mt++) {
            int r = arow + mt * 16;
            a[mt][0] = sAu[r * PAD + k0];
            a[mt][1] = sAu[(r + 8) * PAD + k0];
            a[mt][2] = sAu[r * PAD + k0 + 4];
            a[mt][3] = sAu[(r + 8) * PAD + k0 + 4];
        }
#pragma unroll
        for (int nt = 0; nt < NT; nt++) {
            int n = bcol0 + nt * 8 + ((threadIdx.x & 31) >> 2);
            uint32_t b0 = sWu[n * PAD + k0];
            uint32_t b1 = sWu[n * PAD + k0 + 4];
#pragma unroll
            for (int mt = 0; mt < 2; mt++)
                mma_tf32(d[mt][nt], a[mt], b0, b1);
        }
    }
}

// ---------------- fused 2-layer MLP ------------------------------------------
template <int M2, int ACT2>
__global__ __launch_bounds__(512, 1)
void mlp_fused(const float* __restrict__ A,
               const float* __restrict__ Wt1, const float* __restrict__ b1,
               const float* __restrict__ Wt2, const float* __restrict__ b2,
               float* __restrict__ Cout, int N)
{
    constexpr int NT1 = 8;
    constexpr int NT2 = M2 / 16;

    extern __shared__ float smem[];
    float* sA  = smem;                 // [256][PAD] : A tile, then intermediate
    float* sW  = smem + 256 * PAD;     // [128][PAD] : W1, then W2
    float* sB1 = sW + 128 * PAD;
    float* sB2 = sB1 + 128;

    const int tid  = threadIdx.x;
    const int row0 = blockIdx.x * 256;

    for (int i = tid; i < 128 * 32; i += 512) {
        int n = i >> 5, k4 = i & 31;
        *(float4*)(sW + n * PAD + k4 * 4) = ((const float4*)Wt1)[i];
    }
    if (tid < 128) sB1[tid] = b1[tid];
    if (tid < M2)  sB2[tid] = b2[tid];

    for (int i = tid; i < 256 * 32; i += 512) {
        int r = i >> 5, k4 = i & 31;
        float4 v = make_float4(0.f, 0.f, 0.f, 0.f);
        if (row0 + r < N) v = ((const float4*)A)[(size_t)(row0 + r) * 32 + k4];
        v.x = tf32r(v.x); v.y = tf32r(v.y); v.z = tf32r(v.z); v.w = tf32r(v.w);
        *(float4*)(sA + r * PAD + k4 * 4) = v;
    }
    __syncthreads();

    const int wid    = tid >> 5;
    const int lane   = tid & 31;
    const int warp_n = wid >> 3;
    const int warp_m = wid & 7;
    const int gid    = lane >> 2;
    const int tig    = lane & 3;
    const int arow   = warp_m * 32 + gid;

    const uint32_t* sAu = (const uint32_t*)sA;
    const uint32_t* sWu = (const uint32_t*)sW;

    // GEMM1 + bias + relu (tf32-rounded, kept in registers)
    float d1[2][NT1][4];
    mma_block<NT1>(sAu, sWu, arow, warp_n * 64, d1);
#pragma unroll
    for (int mt = 0; mt < 2; mt++)
#pragma unroll
        for (int nt = 0; nt < NT1; nt++)
#pragma unroll
            for (int half = 0; half < 2; half++) {
                int col = warp_n * 64 + nt * 8 + tig * 2;
                float v0 = fmaxf(d1[mt][nt][half * 2 + 0] + sB1[col], 0.f);
                float v1 = fmaxf(d1[mt][nt][half * 2 + 1] + sB1[col + 1], 0.f);
                d1[mt][nt][half * 2 + 0] = tf32r(v0);
                d1[mt][nt][half * 2 + 1] = tf32r(v1);
            }
    __syncthreads();

    // intermediate -> sA; W2 -> sW
#pragma unroll
    for (int mt = 0; mt < 2; mt++) {
        int rb = warp_m * 32 + mt * 16 + gid;
#pragma unroll
        for (int half = 0; half < 2; half++) {
            int r = rb + half * 8;
#pragma unroll
            for (int nt = 0; nt < NT1; nt++) {
                int col = warp_n * 64 + nt * 8 + tig * 2;
                *(float2*)(sA + r * PAD + col) =
                    make_float2(d1[mt][nt][half * 2], d1[mt][nt][half * 2 + 1]);
            }
        }
    }
    for (int i = tid; i < M2 * 32; i += 512) {
        int n = i >> 5, k4 = i & 31;
        *(float4*)(sW + n * PAD + k4 * 4) = ((const float4*)Wt2)[i];
    }
    __syncthreads();

    // GEMM2 + bias + act2 -> global
    float d2[2][NT2][4];
    mma_block<NT2>(sAu, sWu, arow, warp_n * (M2 / 2), d2);
#pragma unroll
    for (int mt = 0; mt < 2; mt++) {
        int rbase = row0 + warp_m * 32 + mt * 16 + gid;
#pragma unroll
        for (int half = 0; half < 2; half++) {
            int r = rbase + half * 8;
            if (r < N) {
#pragma unroll
                for (int nt = 0; nt < NT2; nt++) {
                    int col = warp_n * (M2 / 2) + nt * 8 + tig * 2;
                    float v0 = d2[mt][nt][half * 2 + 0] + sB2[col];
                    float v1 = d2[mt][nt][half * 2 + 1] + sB2[col + 1];
                    if (ACT2 == 2) {
                        v0 = (v0 > 0.f) ? v0 : expm1f(v0);
                        v1 = (v1 > 0.f) ? v1 : expm1f(v1);
                    }
                    *(float2*)(Cout + (size_t)r * M2 + col) = make_float2(v0, v1);
                }
            }
        }
    }
}

// ---------------------------------------------------------------------------
extern "C" void kernel_launch(void* const* d_in, const int* in_sizes, int n_in,
                              void* d_out, int out_size) {
    const float* x   = (const float*)d_in[0];
    const float* Q   = (const float*)d_in[1];
    const float* w1a = (const float*)d_in[2];
    const float* b1a = (const float*)d_in[3];
    const float* w1b = (const float*)d_in[4];
    const float* b1b = (const float*)d_in[5];
    const float* w2a = (const float*)d_in[6];
    const float* b2a = (const float*)d_in[7];
    const float* w2b = (const float*)d_in[8];
    const float* b2b = (const float*)d_in[9];
    const int*   ei  = (const int*)d_in[10];

    int N = in_sizes[0] / 128;
    int E = in_sizes[10] / 2;
    int C = in_sizes[9];
    int qn = in_sizes[1];

    float* out = (float*)d_out;
    float *buf0, *buf1, *wt;
    int *adj, *rowStart, *cursor, *deg;
    cudaGetSymbolAddress((void**)&buf0, g_buf0);
    cudaGetSymbolAddress((void**)&buf1, g_buf1);
    cudaGetSymbolAddress((void**)&wt,   g_wt);
    cudaGetSymbolAddress((void**)&adj,      g_adj);
    cudaGetSymbolAddress((void**)&rowStart, g_rowStart);
    cudaGetSymbolAddress((void**)&cursor,   g_cursor);
    cudaGetSymbolAddress((void**)&deg,      g_deg);

    float* wt1a = wt;
    float* wt1b = wt + 16384;
    float* wt2a = wt + 32768;
    float* wt2b = wt + 49152;

    const int* srcI = ei;
    const int* dstI = ei + E;

    const int smemL = (256 * PAD + 128 * PAD + 128 + 128) * (int)sizeof(float);  // ~203 KB
    cudaFuncSetAttribute(mlp_fused<128, 2>, cudaFuncAttributeMaxDynamicSharedMemorySize, smemL);
    cudaFuncSetAttribute(mlp_fused<64, 0>,  cudaFuncAttributeMaxDynamicSharedMemorySize, smemL);

    // ---- Q copy split across all five big launches ----
    int q4total = qn / 4;                       // float4 count
    int qA = q4total / 4;                       // hist launch
    int qB = q4total / 5;                       // scan launch
    int qC = q4total / 5;                       // fill launch
    int qD = (q4total - qA - qB - qC) / 2;      // gather1
    int qE = q4total - qA - qB - qC - qD;       // gather2
    const float4* qs = (const float4*)Q;
    float4* qd = (float4*)(out + (size_t)N * C);

    int histBlocks = (E + 255) / 256;
    int tpBlocks   = 224;                       // 57344 / 256
    int fillBlocks = (E + 255) / 256;
    int gatBlocks  = (N * 32 + 255) / 256;
    int copyBlocks = 1200;
    int mlpBlocks  = (N + 255) / 256;

    // ---- CSR build (+ transpose + copy folded in) ----
    cudaMemsetAsync(deg, 0, N * sizeof(int), 0);
    hist_tp_copy_kernel<<<histBlocks + tpBlocks + copyBlocks, 256>>>(
        dstI, deg, E, histBlocks, w1a, w1b, w2a, w2b, wt, tpBlocks,
        qs, qd, qA);
    scan_copy_kernel<<<1 + copyBlocks, 1024>>>(deg, rowStart, cursor, N,
                                               qs + qA, qd + qA, qB);
    fill_copy_kernel<<<fillBlocks + copyBlocks, 256>>>(
        srcI, dstI, cursor, adj, E, fillBlocks, qs + qA + qB, qd + qA + qB, qC);

    // ---- layer 1 ----
    gather_copy_kernel<<<gatBlocks + copyBlocks, 256>>>(
        (const float4*)x, rowStart, adj, (float4*)buf0, N, gatBlocks,
        qs + qA + qB + qC, qd + qA + qB + qC, qD);
    mlp_fused<128, 2><<<mlpBlocks, 512, smemL>>>(buf0, wt1a, b1a, wt1b, b1b, buf1, N);

    // ---- layer 2 (h in buf1) ----
    gather_copy_kernel<<<gatBlocks + copyBlocks, 256>>>(
        (const float4*)buf1, rowStart, adj, (float4*)buf0, N, gatBlocks,
        qs + qA + qB + qC + qD, qd + qA + qB + qC + qD, qE);
    mlp_fused<64, 0><<<mlpBlocks, 512, smemL>>>(buf0, wt2a, b2a, wt2b, b2b, out, N);
}

// round 12
// speedup vs baseline: 1.2594x; 1.0057x over previous
#include <cuda_runtime.h>
#include <cstdint>
#include <math.h>

// ---------------------------------------------------------------------------
// GIN_Net forward on GB300 (sm_103a).
// Per layer: high-occupancy CSR gather (MLP=8), then fused MLP (GEMM1+relu ->
// smem -> GEMM2+act) on mma.sync tf32. Q pass-through copy spread as block
// ranges across ALL launches (build + gathers + MLP tails).
// ---------------------------------------------------------------------------

#define MAX_N 100000
#define MAX_E 1600000
#define HDIM  128
#define PAD   132

__device__ float g_buf0[MAX_N * HDIM];
__device__ float g_buf1[MAX_N * HDIM];
__device__ float g_wt[3 * 128 * 128 + 64 * 128];   // w1a^T,w1b^T,w2a^T,w2b^T (tf32)
__device__ int   g_adj[MAX_E];
__device__ __align__(16) int g_rowStart[MAX_N + 1];
__device__ __align__(16) int g_cursor[MAX_N];
__device__ __align__(16) int g_deg[MAX_N];

__device__ __forceinline__ float tf32r(float x) {
    float y;
    asm("cvt.rna.tf32.f32 %0, %1;" : "=f"(y) : "f"(x));
    return y;
}

__device__ __forceinline__ void mma_tf32(float d[4], const uint32_t a[4],
                                         uint32_t b0, uint32_t b1) {
    asm volatile(
        "mma.sync.aligned.m16n8k8.row.col.f32.tf32.tf32.f32 "
        "{%0,%1,%2,%3}, {%4,%5,%6,%7}, {%8,%9}, {%0,%1,%2,%3};"
        : "+f"(d[0]), "+f"(d[1]), "+f"(d[2]), "+f"(d[3])
        : "r"(a[0]), "r"(a[1]), "r"(a[2]), "r"(a[3]), "r"(b0), "r"(b1));
}

// grid-stride float4 copy helper for folded copy block-ranges
__device__ __forceinline__ void copy_range(int blk0,
                                           const float4* __restrict__ qsrc,
                                           float4* __restrict__ qdst, int qcount4) {
    long i = (long)(blockIdx.x - blk0) * blockDim.x + threadIdx.x;
    long stride = (long)(gridDim.x - blk0) * blockDim.x;
    for (; i < qcount4; i += stride) qdst[i] = qsrc[i];
}

// ---------------- build: hist + weight transpose + copy ----------------------
__global__ void hist_tp_copy_kernel(const int* __restrict__ dst, int* __restrict__ deg, int E,
                                    int histBlocks,
                                    const float* __restrict__ w1a, const float* __restrict__ w1b,
                                    const float* __restrict__ w2a, const float* __restrict__ w2b,
                                    float* __restrict__ wt, int tpBlocks,
                                    const float4* __restrict__ qsrc, float4* __restrict__ qdst,
                                    int qcount4) {
    int b = blockIdx.x;
    if (b < histBlocks) {
        int e = b * blockDim.x + threadIdx.x;
        if (e < E) atomicAdd(&deg[dst[e]], 1);
        return;
    }
    if (b < histBlocks + tpBlocks) {
        int i = (b - histBlocks) * blockDim.x + threadIdx.x;
        if (i < 49152) {
            const float* W = (i < 16384) ? w1a : (i < 32768) ? w1b : w2a;
            int li = i & 16383;
            int n = li >> 7, k = li & 127;
            wt[i] = tf32r(W[k * 128 + n]);
        } else if (i < 57344) {
            int li = i - 49152;
            int n = li >> 7, k = li & 127;
            wt[i] = tf32r(w2b[k * 64 + n]);
        }
        return;
    }
    copy_range(histBlocks + tpBlocks, qsrc, qdst, qcount4);
}

// ---------------- build: scan (block 0) + copy (rest) ------------------------
__global__ void scan_copy_kernel(const int* __restrict__ deg, int* __restrict__ rowStart,
                                 int* __restrict__ cursor, int N,
                                 const float4* __restrict__ qsrc, float4* __restrict__ qdst,
                                 int qcount4) {
    if (blockIdx.x != 0) { copy_range(1, qsrc, qdst, qcount4); return; }

    __shared__ int warpSums[32];
    __shared__ int running;
    int tid = threadIdx.x, lane = tid & 31, wid = tid >> 5;
    if (tid == 0) running = 0;
    __syncthreads();
    for (int base = 0; base < N; base += 4096) {
        int i0 = base + tid * 4;
        int v0 = 0, v1 = 0, v2 = 0, v3 = 0;
        if (i0 + 3 < N) {
            int4 t = *(const int4*)(deg + i0);
            v0 = t.x; v1 = t.y; v2 = t.z; v3 = t.w;
        } else {
            if (i0 + 0 < N) v0 = deg[i0 + 0];
            if (i0 + 1 < N) v1 = deg[i0 + 1];
            if (i0 + 2 < N) v2 = deg[i0 + 2];
            if (i0 + 3 < N) v3 = deg[i0 + 3];
        }
        int s = v0 + v1 + v2 + v3;
        int val = s;
#pragma unroll
        for (int off = 1; off < 32; off <<= 1) {
            int t = __shfl_up_sync(0xffffffffu, val, off);
            if (lane >= off) val += t;
        }
        if (lane == 31) warpSums[wid] = val;
        __syncthreads();
        if (wid == 0) {
            int w = warpSums[lane];
#pragma unroll
            for (int off = 1; off < 32; off <<= 1) {
                int t = __shfl_up_sync(0xffffffffu, w, off);
                if (lane >= off) w += t;
            }
            warpSums[lane] = w;
        }
        __syncthreads();
        int excl = running + ((wid == 0) ? 0 : warpSums[wid - 1]) + val - s;
        int r = excl;
        if (i0 + 0 < N) { rowStart[i0 + 0] = r; cursor[i0 + 0] = r; r += v0; }
        if (i0 + 1 < N) { rowStart[i0 + 1] = r; cursor[i0 + 1] = r; r += v1; }
        if (i0 + 2 < N) { rowStart[i0 + 2] = r; cursor[i0 + 2] = r; r += v2; }
        if (i0 + 3 < N) { rowStart[i0 + 3] = r; cursor[i0 + 3] = r; r += v3; }
        __syncthreads();
        if (tid == 0) running += warpSums[31];
        __syncthreads();
    }
    if (tid == 0) rowStart[N] = running;
}

// ---------------- build: fill + copy -----------------------------------------
__global__ void fill_copy_kernel(const int* __restrict__ src, const int* __restrict__ dst,
                                 int* __restrict__ cursor, int* __restrict__ adj, int E,
                                 int fillBlocks,
                                 const float4* __restrict__ qsrc, float4* __restrict__ qdst,
                                 int qcount4) {
    if ((int)blockIdx.x >= fillBlocks) { copy_range(fillBlocks, qsrc, qdst, qcount4); return; }
    int e = blockIdx.x * blockDim.x + threadIdx.x;
    if (e < E) {
        int p = atomicAdd(&cursor[dst[e]], 1);
        adj[p] = src[e];
    }
}

// ---------------- CSR gather (MLP=8) + folded Q copy -------------------------
__device__ __forceinline__ void add4(float4& a, const float4 b) {
    a.x += b.x; a.y += b.y; a.z += b.z; a.w += b.w;
}

__global__ void gather_copy_kernel(const float4* __restrict__ h4,
                                   const int* __restrict__ rowStart,
                                   const int* __restrict__ adj,
                                   float4* __restrict__ out4, int N, int gatBlocks,
                                   const float4* __restrict__ qsrc,
                                   float4* __restrict__ qdst, int qcount4) {
    if ((int)blockIdx.x >= gatBlocks) { copy_range(gatBlocks, qsrc, qdst, qcount4); return; }
    int warp = (blockIdx.x * blockDim.x + threadIdx.x) >> 5;
    int lane = threadIdx.x & 31;
    if (warp >= N) return;
    int s = __ldg(rowStart + warp);
    int e = __ldg(rowStart + warp + 1);
    float4 acc = h4[(size_t)warp * 32 + lane];   // self term
    int j = s;
    // 8-deep MLP main loop
    for (; j + 7 < e; j += 8) {
        int idx[8];
#pragma unroll
        for (int q = 0; q < 8; q++) idx[q] = __ldg(adj + j + q);
        float4 v[8];
#pragma unroll
        for (int q = 0; q < 8; q++) v[q] = h4[(size_t)idx[q] * 32 + lane];
#pragma unroll
        for (int q = 0; q < 8; q++) add4(acc, v[q]);
    }
    for (; j + 3 < e; j += 4) {
        int n0 = __ldg(adj + j),     n1 = __ldg(adj + j + 1);
        int n2 = __ldg(adj + j + 2), n3 = __ldg(adj + j + 3);
        float4 v0 = h4[(size_t)n0 * 32 + lane];
        float4 v1 = h4[(size_t)n1 * 32 + lane];
        float4 v2 = h4[(size_t)n2 * 32 + lane];
        float4 v3 = h4[(size_t)n3 * 32 + lane];
        add4(acc, v0); add4(acc, v1); add4(acc, v2); add4(acc, v3);
    }
    for (; j < e; j++)
        add4(acc, h4[(size_t)__ldg(adj + j) * 32 + lane]);
    out4[(size_t)warp * 32 + lane] = acc;
}

// ---------------- MMA tile loop (256 rows x cols, 16 warps) -----------------
template <int NT>
__device__ __forceinline__ void mma_block(const uint32_t* __restrict__ sAu,
                                          const uint32_t* __restrict__ sWu,
                                          int arow, int bcol0, float (&d)[2][NT][4]) {
#pragma unroll
    for (int mt = 0; mt < 2; mt++)
#pragma unroll
        for (int nt = 0; nt < NT; nt++)
#pragma unroll
            for (int j = 0; j < 4; j++) d[mt][nt][j] = 0.f;

#pragma unroll
    for (int kt = 0; kt < 16; kt++) {
        const int k0 = kt * 8 + (threadIdx.x & 3);
        uint32_t a[2][4];
#pragma unroll
        for (int mt = 0; mt < 2; mt++) {
            int r = arow + mt * 16;
            a[mt][0] = sAu[r * PAD + k0];
            a[mt][1] = sAu[(r + 8) * PAD + k0];
            a[mt][2] = sAu[r * PAD + k0 + 4];
            a[mt][3] = sAu[(r + 8) * PAD + k0 + 4];
        }
#pragma unroll
        for (int nt = 0; nt < NT; nt++) {
            int n = bcol0 + nt * 8 + ((threadIdx.x & 31) >> 2);
            uint32_t b0 = sWu[n * PAD + k0];
            uint32_t b1 = sWu[n * PAD + k0 + 4];
#pragma unroll
            for (int mt = 0; mt < 2; mt++)
                mma_tf32(d[mt][nt], a[mt], b0, b1);
        }
    }
}

// ---------------- fused 2-layer MLP (+ tail copy blocks) ---------------------
template <int M2, int ACT2>
__global__ __launch_bounds__(512, 1)
void mlp_fused(const float* __restrict__ A,
               const float* __restrict__ Wt1, const float* __restrict__ b1,
               const float* __restrict__ Wt2, const float* __restrict__ b2,
               float* __restrict__ Cout, int N, int mlpBlocks,
               const float4* __restrict__ qsrc, float4* __restrict__ qdst, int qcount4)
{
    constexpr int NT1 = 8;
    constexpr int NT2 = M2 / 16;

    if ((int)blockIdx.x >= mlpBlocks) { copy_range(mlpBlocks, qsrc, qdst, qcount4); return; }

    extern __shared__ float smem[];
    float* sA  = smem;                 // [256][PAD] : A tile, then intermediate
    float* sW  = smem + 256 * PAD;     // [128][PAD] : W1, then W2
    float* sB1 = sW + 128 * PAD;
    float* sB2 = sB1 + 128;

    const int tid  = threadIdx.x;
    const int row0 = blockIdx.x * 256;

    for (int i = tid; i < 128 * 32; i += 512) {
        int n = i >> 5, k4 = i & 31;
        *(float4*)(sW + n * PAD + k4 * 4) = ((const float4*)Wt1)[i];
    }
    if (tid < 128) sB1[tid] = b1[tid];
    if (tid < M2)  sB2[tid] = b2[tid];

    for (int i = tid; i < 256 * 32; i += 512) {
        int r = i >> 5, k4 = i & 31;
        float4 v = make_float4(0.f, 0.f, 0.f, 0.f);
        if (row0 + r < N) v = ((const float4*)A)[(size_t)(row0 + r) * 32 + k4];
        v.x = tf32r(v.x); v.y = tf32r(v.y); v.z = tf32r(v.z); v.w = tf32r(v.w);
        *(float4*)(sA + r * PAD + k4 * 4) = v;
    }
    __syncthreads();

    const int wid    = tid >> 5;
    const int lane   = tid & 31;
    const int warp_n = wid >> 3;
    const int warp_m = wid & 7;
    const int gid    = lane >> 2;
    const int tig    = lane & 3;
    const int arow   = warp_m * 32 + gid;

    const uint32_t* sAu = (const uint32_t*)sA;
    const uint32_t* sWu = (const uint32_t*)sW;

    // GEMM1 + bias + relu (tf32-rounded, kept in registers)
    float d1[2][NT1][4];
    mma_block<NT1>(sAu, sWu, arow, warp_n * 64, d1);
#pragma unroll
    for (int mt = 0; mt < 2; mt++)
#pragma unroll
        for (int nt = 0; nt < NT1; nt++)
#pragma unroll
            for (int half = 0; half < 2; half++) {
                int col = warp_n * 64 + nt * 8 + tig * 2;
                float v0 = fmaxf(d1[mt][nt][half * 2 + 0] + sB1[col], 0.f);
                float v1 = fmaxf(d1[mt][nt][half * 2 + 1] + sB1[col + 1], 0.f);
                d1[mt][nt][half * 2 + 0] = tf32r(v0);
                d1[mt][nt][half * 2 + 1] = tf32r(v1);
            }
    __syncthreads();

    // intermediate -> sA; W2 -> sW
#pragma unroll
    for (int mt = 0; mt < 2; mt++) {
        int rb = warp_m * 32 + mt * 16 + gid;
#pragma unroll
        for (int half = 0; half < 2; half++) {
            int r = rb + half * 8;
#pragma unroll
            for (int nt = 0; nt < NT1; nt++) {
                int col = warp_n * 64 + nt * 8 + tig * 2;
                *(float2*)(sA + r * PAD + col) =
                    make_float2(d1[mt][nt][half * 2], d1[mt][nt][half * 2 + 1]);
            }
        }
    }
    for (int i = tid; i < M2 * 32; i += 512) {
        int n = i >> 5, k4 = i & 31;
        *(float4*)(sW + n * PAD + k4 * 4) = ((const float4*)Wt2)[i];
    }
    __syncthreads();

    // GEMM2 + bias + act2 -> global
    float d2[2][NT2][4];
    mma_block<NT2>(sAu, sWu, arow, warp_n * (M2 / 2), d2);
#pragma unroll
    for (int mt = 0; mt < 2; mt++) {
        int rbase = row0 + warp_m * 32 + mt * 16 + gid;
#pragma unroll
        for (int half = 0; half < 2; half++) {
            int r = rbase + half * 8;
            if (r < N) {
#pragma unroll
                for (int nt = 0; nt < NT2; nt++) {
                    int col = warp_n * (M2 / 2) + nt * 8 + tig * 2;
                    float v0 = d2[mt][nt][half * 2 + 0] + sB2[col];
                    float v1 = d2[mt][nt][half * 2 + 1] + sB2[col + 1];
                    if (ACT2 == 2) {
                        v0 = (v0 > 0.f) ? v0 : expm1f(v0);
                        v1 = (v1 > 0.f) ? v1 : expm1f(v1);
                    }
                    *(float2*)(Cout + (size_t)r * M2 + col) = make_float2(v0, v1);
                }
            }
        }
    }
}

// ---------------------------------------------------------------------------
extern "C" void kernel_launch(void* const* d_in, const int* in_sizes, int n_in,
                              void* d_out, int out_size) {
    const float* x   = (const float*)d_in[0];
    const float* Q   = (const float*)d_in[1];
    const float* w1a = (const float*)d_in[2];
    const float* b1a = (const float*)d_in[3];
    const float* w1b = (const float*)d_in[4];
    const float* b1b = (const float*)d_in[5];
    const float* w2a = (const float*)d_in[6];
    const float* b2a = (const float*)d_in[7];
    const float* w2b = (const float*)d_in[8];
    const float* b2b = (const float*)d_in[9];
    const int*   ei  = (const int*)d_in[10];

    int N = in_sizes[0] / 128;
    int E = in_sizes[10] / 2;
    int C = in_sizes[9];
    int qn = in_sizes[1];

    float* out = (float*)d_out;
    float *buf0, *buf1, *wt;
    int *adj, *rowStart, *cursor, *deg;
    cudaGetSymbolAddress((void**)&buf0, g_buf0);
    cudaGetSymbolAddress((void**)&buf1, g_buf1);
    cudaGetSymbolAddress((void**)&wt,   g_wt);
    cudaGetSymbolAddress((void**)&adj,      g_adj);
    cudaGetSymbolAddress((void**)&rowStart, g_rowStart);
    cudaGetSymbolAddress((void**)&cursor,   g_cursor);
    cudaGetSymbolAddress((void**)&deg,      g_deg);

    float* wt1a = wt;
    float* wt1b = wt + 16384;
    float* wt2a = wt + 32768;
    float* wt2b = wt + 49152;

    const int* srcI = ei;
    const int* dstI = ei + E;

    const int smemL = (256 * PAD + 128 * PAD + 128 + 128) * (int)sizeof(float);  // ~203 KB
    cudaFuncSetAttribute(mlp_fused<128, 2>, cudaFuncAttributeMaxDynamicSharedMemorySize, smemL);
    cudaFuncSetAttribute(mlp_fused<64, 0>,  cudaFuncAttributeMaxDynamicSharedMemorySize, smemL);

    // ---- Q copy split: build 55%, gathers 10% each, MLPs 12-13% ----
    int q4total = qn / 4;
    int qA = q4total / 5;                                      // hist
    int qB = (q4total * 3) / 20;                               // scan
    int qC = q4total / 5;                                      // fill
    int qD = q4total / 10;                                     // gather1
    int qM1 = (q4total * 3) / 25;                              // mlp1
    int qE = q4total / 10;                                     // gather2
    int qM2 = q4total - qA - qB - qC - qD - qM1 - qE;          // mlp2 (rest)
    const float4* qs = (const float4*)Q;
    float4* qd = (float4*)(out + (size_t)N * C);

    int histBlocks = (E + 255) / 256;
    int tpBlocks   = 224;
    int fillBlocks = (E + 255) / 256;
    int gatBlocks  = (N * 32 + 255) / 256;
    int copyBlocks = 1200;
    int mlpBlocks  = (N + 255) / 256;
    int mlpCopyBlocks = 160;

    long o = 0;

    // ---- CSR build (+ transpose + copy folded in) ----
    cudaMemsetAsync(deg, 0, N * sizeof(int), 0);
    hist_tp_copy_kernel<<<histBlocks + tpBlocks + copyBlocks, 256>>>(
        dstI, deg, E, histBlocks, w1a, w1b, w2a, w2b, wt, tpBlocks, qs + o, qd + o, qA);
    o += qA;
    scan_copy_kernel<<<1 + copyBlocks, 1024>>>(deg, rowStart, cursor, N, qs + o, qd + o, qB);
    o += qB;
    fill_copy_kernel<<<fillBlocks + copyBlocks, 256>>>(
        srcI, dstI, cursor, adj, E, fillBlocks, qs + o, qd + o, qC);
    o += qC;

    // ---- layer 1 ----
    gather_copy_kernel<<<gatBlocks + copyBlocks, 256>>>(
        (const float4*)x, rowStart, adj, (float4*)buf0, N, gatBlocks, qs + o, qd + o, qD);
    o += qD;
    mlp_fused<128, 2><<<mlpBlocks + mlpCopyBlocks, 512, smemL>>>(
        buf0, wt1a, b1a, wt1b, b1b, buf1, N, mlpBlocks, qs + o, qd + o, qM1);
    o += qM1;

    // ---- layer 2 (h in buf1) ----
    gather_copy_kernel<<<gatBlocks + copyBlocks, 256>>>(
        (const float4*)buf1, rowStart, adj, (float4*)buf0, N, gatBlocks, qs + o, qd + o, qE);
    o += qE;
    mlp_fused<64, 0><<<mlpBlocks + mlpCopyBlocks, 512, smemL>>>(
        buf0, wt2a, b2a, wt2b, b2b, out, N, mlpBlocks, qs + o, qd + o, qM2);
}

// round 15
// speedup vs baseline: 1.3588x; 1.0789x over previous
#include <cuda_runtime.h>
#include <cuda_fp16.h>
#include <cstdint>
#include <math.h>

// ---------------------------------------------------------------------------
// GIN_Net forward on GB300 (sm_103a).
// Features for aggregation stored fp16 (same 10-bit mantissa as the tf32 the
// GEMMs already round to). Per layer: CSR gather (fp16 in, fp32 out), fused
// MLP (GEMM1+relu -> smem -> GEMM2+act) on mma.sync tf32. Q pass-through copy
// spread across build + MLP launches using 256-bit evict_first accesses.
// ---------------------------------------------------------------------------

#define MAX_N 100000
#define MAX_E 1600000
#define HDIM  128
#define PAD   132

__device__ float g_buf0[MAX_N * HDIM];             // fp32 agg (gather out / mlp in)
__device__ float g_buf1[MAX_N * HDIM];             // fp32 agg layer 2
__device__ uint2 g_h16[MAX_N * 32];                // fp16 features (x16, then h16)
__device__ float g_wt[3 * 128 * 128 + 64 * 128];   // w1a^T,w1b^T,w2a^T,w2b^T (tf32)
__device__ int   g_adj[MAX_E];
__device__ __align__(16) int g_rowStart[MAX_N + 1];
__device__ __align__(16) int g_cursor[MAX_N];
__device__ __align__(16) int g_deg[MAX_N];

__device__ __forceinline__ float tf32r(float x) {
    float y;
    asm("cvt.rna.tf32.f32 %0, %1;" : "=f"(y) : "f"(x));
    return y;
}

__device__ __forceinline__ void mma_tf32(float d[4], const uint32_t a[4],
                                         uint32_t b0, uint32_t b1) {
    asm volatile(
        "mma.sync.aligned.m16n8k8.row.col.f32.tf32.tf32.f32 "
        "{%0,%1,%2,%3}, {%4,%5,%6,%7}, {%8,%9}, {%0,%1,%2,%3};"
        : "+f"(d[0]), "+f"(d[1]), "+f"(d[2]), "+f"(d[3])
        : "r"(a[0]), "r"(a[1]), "r"(a[2]), "r"(a[3]), "r"(b0), "r"(b1));
}

// ---- 256-bit evict_first copy helpers (v4.u64 is required for L2 hints) ----
__device__ __forceinline__ void copy32B_ef(const ulonglong4* src, ulonglong4* dst) {
    unsigned long long a, b, c, d;
    asm volatile("ld.global.L2::evict_first.v4.u64 {%0,%1,%2,%3}, [%4];"
                 : "=l"(a), "=l"(b), "=l"(c), "=l"(d) : "l"(src));
    asm volatile("st.global.L2::evict_first.v4.u64 [%0], {%1,%2,%3,%4};"
                 :: "l"(dst), "l"(a), "l"(b), "l"(c), "l"(d) : "memory");
}

__device__ __forceinline__ void acc_h2(float4& acc, uint2 u) {
    __half2 ha = *(__half2*)&u.x;
    __half2 hb = *(__half2*)&u.y;
    float2 fa = __half22float2(ha);
    float2 fb = __half22float2(hb);
    acc.x += fa.x; acc.y += fa.y; acc.z += fb.x; acc.w += fb.y;
}

// grid-stride 32B copy (evict_first both ways: don't pollute L2)
__device__ __forceinline__ void copy_range(int blk0,
                                           const ulonglong4* __restrict__ qsrc,
                                           ulonglong4* __restrict__ qdst, int qcount8) {
    long i = (long)(blockIdx.x - blk0) * blockDim.x + threadIdx.x;
    long stride = (long)(gridDim.x - blk0) * blockDim.x;
    for (; i < qcount8; i += stride) copy32B_ef(qsrc + i, qdst + i);
}

// ---------------- build: hist + x->fp16 + weight transpose + copy ------------
__global__ void hist_xc_tp_copy_kernel(const int* __restrict__ dst, int* __restrict__ deg, int E,
                                       int histBlocks,
                                       const float4* __restrict__ x4, uint2* __restrict__ x16,
                                       int n32, int xcBlocks,
                                       const float* __restrict__ w1a, const float* __restrict__ w1b,
                                       const float* __restrict__ w2a, const float* __restrict__ w2b,
                                       float* __restrict__ wt, int tpBlocks,
                                       const ulonglong4* __restrict__ qsrc,
                                       ulonglong4* __restrict__ qdst, int qcount8) {
    int b = blockIdx.x;
    if (b < histBlocks) {
        int e = b * blockDim.x + threadIdx.x;
        if (e < E) atomicAdd(&deg[dst[e]], 1);
        return;
    }
    b -= histBlocks;
    if (b < xcBlocks) {
        int i = b * blockDim.x + threadIdx.x;
        if (i < n32) {
            float4 v = x4[i];
            __half2 ha = __floats2half2_rn(v.x, v.y);
            __half2 hb = __floats2half2_rn(v.z, v.w);
            uint2 u;
            u.x = *(uint32_t*)&ha;
            u.y = *(uint32_t*)&hb;
            x16[i] = u;
        }
        return;
    }
    b -= xcBlocks;
    if (b < tpBlocks) {
        int i = b * blockDim.x + threadIdx.x;
        if (i < 49152) {
            const float* W = (i < 16384) ? w1a : (i < 32768) ? w1b : w2a;
            int li = i & 16383;
            int n = li >> 7, k = li & 127;
            wt[i] = tf32r(W[k * 128 + n]);
        } else if (i < 57344) {
            int li = i - 49152;
            int n = li >> 7, k = li & 127;
            wt[i] = tf32r(w2b[k * 64 + n]);
        }
        return;
    }
    copy_range(histBlocks + xcBlocks + tpBlocks, qsrc, qdst, qcount8);
}

// ---------------- build: scan (block 0) + copy (rest) ------------------------
__global__ void scan_copy_kernel(const int* __restrict__ deg, int* __restrict__ rowStart,
                                 int* __restrict__ cursor, int N,
                                 const ulonglong4* __restrict__ qsrc,
                                 ulonglong4* __restrict__ qdst, int qcount8) {
    if (blockIdx.x != 0) { copy_range(1, qsrc, qdst, qcount8); return; }

    __shared__ int warpSums[32];
    __shared__ int running;
    int tid = threadIdx.x, lane = tid & 31, wid = tid >> 5;
    if (tid == 0) running = 0;
    __syncthreads();
    for (int base = 0; base < N; base += 4096) {
        int i0 = base + tid * 4;
        int v0 = 0, v1 = 0, v2 = 0, v3 = 0;
        if (i0 + 3 < N) {
            int4 t = *(const int4*)(deg + i0);
            v0 = t.x; v1 = t.y; v2 = t.z; v3 = t.w;
        } else {
            if (i0 + 0 < N) v0 = deg[i0 + 0];
            if (i0 + 1 < N) v1 = deg[i0 + 1];
            if (i0 + 2 < N) v2 = deg[i0 + 2];
            if (i0 + 3 < N) v3 = deg[i0 + 3];
        }
        int s = v0 + v1 + v2 + v3;
        int val = s;
#pragma unroll
        for (int off = 1; off < 32; off <<= 1) {
            int t = __shfl_up_sync(0xffffffffu, val, off);
            if (lane >= off) val += t;
        }
        if (lane == 31) warpSums[wid] = val;
        __syncthreads();
        if (wid == 0) {
            int w = warpSums[lane];
#pragma unroll
            for (int off = 1; off < 32; off <<= 1) {
                int t = __shfl_up_sync(0xffffffffu, w, off);
                if (lane >= off) w += t;
            }
            warpSums[lane] = w;
        }
        __syncthreads();
        int excl = running + ((wid == 0) ? 0 : warpSums[wid - 1]) + val - s;
        int r = excl;
        if (i0 + 0 < N) { rowStart[i0 + 0] = r; cursor[i0 + 0] = r; r += v0; }
        if (i0 + 1 < N) { rowStart[i0 + 1] = r; cursor[i0 + 1] = r; r += v1; }
        if (i0 + 2 < N) { rowStart[i0 + 2] = r; cursor[i0 + 2] = r; r += v2; }
        if (i0 + 3 < N) { rowStart[i0 + 3] = r; cursor[i0 + 3] = r; r += v3; }
        __syncthreads();
        if (tid == 0) running += warpSums[31];
        __syncthreads();
    }
    if (tid == 0) rowStart[N] = running;
}

// ---------------- build: fill + copy -----------------------------------------
__global__ void fill_copy_kernel(const int* __restrict__ src, const int* __restrict__ dst,
                                 int* __restrict__ cursor, int* __restrict__ adj, int E,
                                 int fillBlocks,
                                 const ulonglong4* __restrict__ qsrc,
                                 ulonglong4* __restrict__ qdst, int qcount8) {
    if ((int)blockIdx.x >= fillBlocks) { copy_range(fillBlocks, qsrc, qdst, qcount8); return; }
    int e = blockIdx.x * blockDim.x + threadIdx.x;
    if (e < E) {
        int p = atomicAdd(&cursor[dst[e]], 1);
        adj[p] = src[e];
    }
}

// ---------------- CSR gather: fp16 in, fp32 out ------------------------------
// warp per row; lane covers 4 features (uint2 = 4 halves); MLP depth 8.
__global__ void gather_kernel(const uint2* __restrict__ h16,
                              const int* __restrict__ rowStart,
                              const int* __restrict__ adj,
                              float4* __restrict__ out4, int N) {
    int warp = (blockIdx.x * blockDim.x + threadIdx.x) >> 5;
    int lane = threadIdx.x & 31;
    if (warp >= N) return;
    int s = __ldg(rowStart + warp);
    int e = __ldg(rowStart + warp + 1);
    float4 acc = make_float4(0.f, 0.f, 0.f, 0.f);
    acc_h2(acc, __ldg(h16 + (size_t)warp * 32 + lane));   // self term
    int j = s;
    for (; j + 7 < e; j += 8) {
        int idx[8];
#pragma unroll
        for (int q = 0; q < 8; q++) idx[q] = __ldg(adj + j + q);
        uint2 v[8];
#pragma unroll
        for (int q = 0; q < 8; q++) v[q] = __ldg(h16 + (size_t)idx[q] * 32 + lane);
#pragma unroll
        for (int q = 0; q < 8; q++) acc_h2(acc, v[q]);
    }
    for (; j + 3 < e; j += 4) {
        int i0 = __ldg(adj + j),     i1 = __ldg(adj + j + 1);
        int i2 = __ldg(adj + j + 2), i3 = __ldg(adj + j + 3);
        uint2 v0 = __ldg(h16 + (size_t)i0 * 32 + lane);
        uint2 v1 = __ldg(h16 + (size_t)i1 * 32 + lane);
        uint2 v2 = __ldg(h16 + (size_t)i2 * 32 + lane);
        uint2 v3 = __ldg(h16 + (size_t)i3 * 32 + lane);
        acc_h2(acc, v0); acc_h2(acc, v1); acc_h2(acc, v2); acc_h2(acc, v3);
    }
    for (; j < e; j++)
        acc_h2(acc, __ldg(h16 + (size_t)__ldg(adj + j) * 32 + lane));
    out4[(size_t)warp * 32 + lane] = acc;
}

// ---------------- MMA tile loop (256 rows x cols, 16 warps) -----------------
template <int NT>
__device__ __forceinline__ void mma_block(const uint32_t* __restrict__ sAu,
                                          const uint32_t* __restrict__ sWu,
                                          int arow, int bcol0, float (&d)[2][NT][4]) {
#pragma unroll
    for (int mt = 0; mt < 2; mt++)
#pragma unroll
        for (int nt = 0; nt < NT; nt++)
#pragma unroll
            for (int j = 0; j < 4; j++) d[mt][nt][j] = 0.f;

#pragma unroll
    for (int kt = 0; kt < 16; kt++) {
        const int k0 = kt * 8 + (threadIdx.x & 3);
        uint32_t a[2][4];
#pragma unroll
        for (int mt = 0; mt < 2; mt++) {
            int r = arow + mt * 16;
            a[mt][0] = sAu[r * PAD + k0];
            a[mt][1] = sAu[(r + 8) * PAD + k0];
            a[mt][2] = sAu[r * PAD + k0 + 4];
            a[mt][3] = sAu[(r + 8) * PAD + k0 + 4];
        }
#pragma unroll
        for (int nt = 0; nt < NT; nt++) {
            int n = bcol0 + nt * 8 + ((threadIdx.x & 31) >> 2);
            uint32_t b0 = sWu[n * PAD + k0];
            uint32_t b1 = sWu[n * PAD + k0 + 4];
#pragma unroll
            for (int mt = 0; mt < 2; mt++)
                mma_tf32(d[mt][nt], a[mt], b0, b1);
        }
    }
}

// ---------------- fused 2-layer MLP (+ tail copy blocks) ---------------------
// OUT_HALF: store result as fp16 rows of 128 halves (layer-1 h output).
template <int M2, int ACT2, int OUT_HALF>
__global__ __launch_bounds__(512, 1)
void mlp_fused(const float* __restrict__ A,
               const float* __restrict__ Wt1, const float* __restrict__ b1,
               const float* __restrict__ Wt2, const float* __restrict__ b2,
               void* __restrict__ CoutV, int N, int mlpBlocks,
               const ulonglong4* __restrict__ qsrc, ulonglong4* __restrict__ qdst, int qcount8)
{
    constexpr int NT1 = 8;
    constexpr int NT2 = M2 / 16;

    if ((int)blockIdx.x >= mlpBlocks) { copy_range(mlpBlocks, qsrc, qdst, qcount8); return; }

    extern __shared__ float smem[];
    float* sA  = smem;                 // [256][PAD] : A tile, then intermediate
    float* sW  = smem + 256 * PAD;     // [128][PAD] : W1, then W2
    float* sB1 = sW + 128 * PAD;
    float* sB2 = sB1 + 128;

    const int tid  = threadIdx.x;
    const int row0 = blockIdx.x * 256;

    for (int i = tid; i < 128 * 32; i += 512) {
        int n = i >> 5, k4 = i & 31;
        *(float4*)(sW + n * PAD + k4 * 4) = ((const float4*)Wt1)[i];
    }
    if (tid < 128) sB1[tid] = b1[tid];
    if (tid < M2)  sB2[tid] = b2[tid];

    for (int i = tid; i < 256 * 32; i += 512) {
        int r = i >> 5, k4 = i & 31;
        float4 v = make_float4(0.f, 0.f, 0.f, 0.f);
        if (row0 + r < N) v = ((const float4*)A)[(size_t)(row0 + r) * 32 + k4];
        v.x = tf32r(v.x); v.y = tf32r(v.y); v.z = tf32r(v.z); v.w = tf32r(v.w);
        *(float4*)(sA + r * PAD + k4 * 4) = v;
    }
    __syncthreads();

    const int wid    = tid >> 5;
    const int lane   = tid & 31;
    const int warp_n = wid >> 3;
    const int warp_m = wid & 7;
    const int gid    = lane >> 2;
    const int tig    = lane & 3;
    const int arow   = warp_m * 32 + gid;

    const uint32_t* sAu = (const uint32_t*)sA;
    const uint32_t* sWu = (const uint32_t*)sW;

    // GEMM1 + bias + relu (tf32-rounded, kept in registers)
    float d1[2][NT1][4];
    mma_block<NT1>(sAu, sWu, arow, warp_n * 64, d1);
#pragma unroll
    for (int mt = 0; mt < 2; mt++)
#pragma unroll
        for (int nt = 0; nt < NT1; nt++)
#pragma unroll
            for (int half = 0; half < 2; half++) {
                int col = warp_n * 64 + nt * 8 + tig * 2;
                float v0 = fmaxf(d1[mt][nt][half * 2 + 0] + sB1[col], 0.f);
                float v1 = fmaxf(d1[mt][nt][half * 2 + 1] + sB1[col + 1], 0.f);
                d1[mt][nt][half * 2 + 0] = tf32r(v0);
                d1[mt][nt][half * 2 + 1] = tf32r(v1);
            }
    __syncthreads();

    // intermediate -> sA; W2 -> sW
#pragma unroll
    for (int mt = 0; mt < 2; mt++) {
        int rb = warp_m * 32 + mt * 16 + gid;
#pragma unroll
        for (int half = 0; half < 2; half++) {
            int r = rb + half * 8;
#pragma unroll
            for (int nt = 0; nt < NT1; nt++) {
                int col = warp_n * 64 + nt * 8 + tig * 2;
                *(float2*)(sA + r * PAD + col) =
                    make_float2(d1[mt][nt][half * 2], d1[mt][nt][half * 2 + 1]);
            }
        }
    }
    for (int i = tid; i < M2 * 32; i += 512) {
        int n = i >> 5, k4 = i & 31;
        *(float4*)(sW + n * PAD + k4 * 4) = ((const float4*)Wt2)[i];
    }
    __syncthreads();

    // GEMM2 + bias + act2 -> global
    float d2[2][NT2][4];
    mma_block<NT2>(sAu, sWu, arow, warp_n * (M2 / 2), d2);
#pragma unroll
    for (int mt = 0; mt < 2; mt++) {
        int rbase = row0 + warp_m * 32 + mt * 16 + gid;
#pragma unroll
        for (int half = 0; half < 2; half++) {
            int r = rbase + half * 8;
            if (r < N) {
#pragma unroll
                for (int nt = 0; nt < NT2; nt++) {
                    int col = warp_n * (M2 / 2) + nt * 8 + tig * 2;
                    float v0 = d2[mt][nt][half * 2 + 0] + sB2[col];
                    float v1 = d2[mt][nt][half * 2 + 1] + sB2[col + 1];
                    if (ACT2 == 2) {
                        v0 = (v0 > 0.f) ? v0 : expm1f(v0);
                        v1 = (v1 > 0.f) ? v1 : expm1f(v1);
                    }
                    if (OUT_HALF) {
                        __half2* hd = (__half2*)((__half*)CoutV + (size_t)r * M2 + col);
                        *hd = __floats2half2_rn(v0, v1);
                    } else {
                        *(float2*)((float*)CoutV + (size_t)r * M2 + col) = make_float2(v0, v1);
                    }
                }
            }
        }
    }
}

// ---------------------------------------------------------------------------
extern "C" void kernel_launch(void* const* d_in, const int* in_sizes, int n_in,
                              void* d_out, int out_size) {
    const float* x   = (const float*)d_in[0];
    const float* Q   = (const float*)d_in[1];
    const float* w1a = (const float*)d_in[2];
    const float* b1a = (const float*)d_in[3];
    const float* w1b = (const float*)d_in[4];
    const float* b1b = (const float*)d_in[5];
    const float* w2a = (const float*)d_in[6];
    const float* b2a = (const float*)d_in[7];
    const float* w2b = (const float*)d_in[8];
    const float* b2b = (const float*)d_in[9];
    const int*   ei  = (const int*)d_in[10];

    int N = in_sizes[0] / 128;
    int E = in_sizes[10] / 2;
    int C = in_sizes[9];
    int qn = in_sizes[1];

    float* out = (float*)d_out;
    float *buf0, *buf1, *wt;
    uint2* h16;
    int *adj, *rowStart, *cursor, *deg;
    cudaGetSymbolAddress((void**)&buf0, g_buf0);
    cudaGetSymbolAddress((void**)&buf1, g_buf1);
    cudaGetSymbolAddress((void**)&h16,  g_h16);
    cudaGetSymbolAddress((void**)&wt,   g_wt);
    cudaGetSymbolAddress((void**)&adj,      g_adj);
    cudaGetSymbolAddress((void**)&rowStart, g_rowStart);
    cudaGetSymbolAddress((void**)&cursor,   g_cursor);
    cudaGetSymbolAddress((void**)&deg,      g_deg);

    float* wt1a = wt;
    float* wt1b = wt + 16384;
    float* wt2a = wt + 32768;
    float* wt2b = wt + 49152;

    const int* srcI = ei;
    const int* dstI = ei + E;

    const int smemL = (256 * PAD + 128 * PAD + 128 + 128) * (int)sizeof(float);  // ~203 KB
    cudaFuncSetAttribute((const void*)mlp_fused<128, 2, 1>, cudaFuncAttributeMaxDynamicSharedMemorySize, smemL);
    cudaFuncSetAttribute((const void*)mlp_fused<64, 0, 0>,  cudaFuncAttributeMaxDynamicSharedMemorySize, smemL);

    // ---- Q copy split (32B units): build 62%, MLPs 38% ----
    int q8total = qn / 8;
    int qA = (q8total * 22) / 100;                 // hist/xc launch
    int qB = (q8total * 20) / 100;                 // scan launch
    int qC = (q8total * 20) / 100;                 // fill launch
    int qM1 = (q8total * 19) / 100;                // mlp1
    int qM2 = q8total - qA - qB - qC - qM1;        // mlp2 (rest)
    const ulonglong4* qs = (const ulonglong4*)Q;
    ulonglong4* qd = (ulonglong4*)(out + (size_t)N * C);

    int n32        = N * 32;
    int histBlocks = (E + 255) / 256;
    int xcBlocks   = (n32 + 255) / 256;
    int tpBlocks   = 224;
    int fillBlocks = (E + 255) / 256;
    int gatBlocks  = (N * 32 + 255) / 256;
    int copyBlocks = 1600;
    int mlpBlocks  = (N + 255) / 256;
    int mlpCopyBlocks = 120;

    long o = 0;

    // ---- CSR build (+ x->fp16 + transpose + copy folded in) ----
    cudaMemsetAsync(deg, 0, N * sizeof(int), 0);
    hist_xc_tp_copy_kernel<<<histBlocks + xcBlocks + tpBlocks + copyBlocks, 256>>>(
        dstI, deg, E, histBlocks,
        (const float4*)x, h16, n32, xcBlocks,
        w1a, w1b, w2a, w2b, wt, tpBlocks,
        qs + o, qd + o, qA);
    o += qA;
    scan_copy_kernel<<<1 + copyBlocks, 1024>>>(deg, rowStart, cursor, N, qs + o, qd + o, qB);
    o += qB;
    fill_copy_kernel<<<fillBlocks + copyBlocks, 256>>>(
        srcI, dstI, cursor, adj, E, fillBlocks, qs + o, qd + o, qC);
    o += qC;

    // ---- layer 1: gather x16 -> buf0 (fp32); mlp -> h16 (fp16) ----
    gather_kernel<<<gatBlocks, 256>>>(h16, rowStart, adj, (float4*)buf0, N);
    mlp_fused<128, 2, 1><<<mlpBlocks + mlpCopyBlocks, 512, smemL>>>(
        buf0, wt1a, b1a, wt1b, b1b, (void*)h16, N, mlpBlocks, qs + o, qd + o, qM1);
    o += qM1;

    // ---- layer 2: gather h16 -> buf1 (fp32); mlp -> out (fp32) ----
    gather_kernel<<<gatBlocks, 256>>>(h16, rowStart, adj, (float4*)buf1, N);
    mlp_fused<64, 0, 0><<<mlpBlocks + mlpCopyBlocks, 512, smemL>>>(
        buf1, wt2a, b2a, wt2b, b2b, (void*)out, N, mlpBlocks, qs + o, qd + o, qM2);
}

// round 16
// speedup vs baseline: 1.5813x; 1.1638x over previous
#include <cuda_runtime.h>
#include <cuda_fp16.h>
#include <cstdint>
#include <math.h>

// ---------------------------------------------------------------------------
// GIN_Net forward on GB300 (sm_103a).
// Everything feeding MMAs is fp16 (same 10-bit mantissa as tf32): features,
// aggregates, weights. GEMMs on mma.sync m16n8k16.f16 with fp32 accumulate.
// Per layer: CSR gather (fp16 in/out, fp32 accum), fused MLP (GEMM1+relu ->
// smem -> GEMM2+act). Q pass-through copy spread across launches with 256-bit
// evict_first accesses.
// ---------------------------------------------------------------------------

#define MAX_N 100000
#define MAX_E 1600000
#define HDIM  128
#define WPR   68          // uint32 words per smem row (64 data + 4 pad)

__device__ float g_buf0[MAX_N * HDIM];             // reused as fp16 agg buffers
__device__ float g_buf1[MAX_N * HDIM];
__device__ uint2 g_h16[MAX_N * 32];                // fp16 features (x16, then h16)
__device__ __align__(16) __half g_wt[3 * 128 * 128 + 64 * 128];  // fp16 W^T
__device__ int   g_adj[MAX_E];
__device__ __align__(16) int g_rowStart[MAX_N + 1];
__device__ __align__(16) int g_cursor[MAX_N];
__device__ __align__(16) int g_deg[MAX_N];

__device__ __forceinline__ void mma_f16(float d[4], const uint32_t a[4],
                                        uint32_t b0, uint32_t b1) {
    asm volatile(
        "mma.sync.aligned.m16n8k16.row.col.f32.f16.f16.f32 "
        "{%0,%1,%2,%3}, {%4,%5,%6,%7}, {%8,%9}, {%0,%1,%2,%3};"
        : "+f"(d[0]), "+f"(d[1]), "+f"(d[2]), "+f"(d[3])
        : "r"(a[0]), "r"(a[1]), "r"(a[2]), "r"(a[3]), "r"(b0), "r"(b1));
}

// ---- 256-bit evict_first copy helpers ---------------------------------------
__device__ __forceinline__ void copy32B_ef(const ulonglong4* src, ulonglong4* dst) {
    unsigned long long a, b, c, d;
    asm volatile("ld.global.L2::evict_first.v4.u64 {%0,%1,%2,%3}, [%4];"
                 : "=l"(a), "=l"(b), "=l"(c), "=l"(d) : "l"(src));
    asm volatile("st.global.L2::evict_first.v4.u64 [%0], {%1,%2,%3,%4};"
                 :: "l"(dst), "l"(a), "l"(b), "l"(c), "l"(d) : "memory");
}

__device__ __forceinline__ void acc_h2(float4& acc, uint2 u) {
    __half2 ha = *(__half2*)&u.x;
    __half2 hb = *(__half2*)&u.y;
    float2 fa = __half22float2(ha);
    float2 fb = __half22float2(hb);
    acc.x += fa.x; acc.y += fa.y; acc.z += fb.x; acc.w += fb.y;
}

__device__ __forceinline__ void copy_range(int blk0,
                                           const ulonglong4* __restrict__ qsrc,
                                           ulonglong4* __restrict__ qdst, int qcount8) {
    long i = (long)(blockIdx.x - blk0) * blockDim.x + threadIdx.x;
    long stride = (long)(gridDim.x - blk0) * blockDim.x;
    for (; i < qcount8; i += stride) copy32B_ef(qsrc + i, qdst + i);
}

// ---------------- build: hist + x->fp16 + weight transpose + copy ------------
__global__ void hist_xc_tp_copy_kernel(const int* __restrict__ dst, int* __restrict__ deg, int E,
                                       int histBlocks,
                                       const float4* __restrict__ x4, uint2* __restrict__ x16,
                                       int n32, int xcBlocks,
                                       const float* __restrict__ w1a, const float* __restrict__ w1b,
                                       const float* __restrict__ w2a, const float* __restrict__ w2b,
                                       __half* __restrict__ wt, int tpBlocks,
                                       const ulonglong4* __restrict__ qsrc,
                                       ulonglong4* __restrict__ qdst, int qcount8) {
    int b = blockIdx.x;
    if (b < histBlocks) {
        int e = b * blockDim.x + threadIdx.x;
        if (e < E) atomicAdd(&deg[dst[e]], 1);
        return;
    }
    b -= histBlocks;
    if (b < xcBlocks) {
        int i = b * blockDim.x + threadIdx.x;
        if (i < n32) {
            float4 v = x4[i];
            __half2 ha = __floats2half2_rn(v.x, v.y);
            __half2 hb = __floats2half2_rn(v.z, v.w);
            uint2 u;
            u.x = *(uint32_t*)&ha;
            u.y = *(uint32_t*)&hb;
            x16[i] = u;
        }
        return;
    }
    b -= xcBlocks;
    if (b < tpBlocks) {
        int i = b * blockDim.x + threadIdx.x;
        if (i < 49152) {
            const float* W = (i < 16384) ? w1a : (i < 32768) ? w1b : w2a;
            int li = i & 16383;
            int n = li >> 7, k = li & 127;
            wt[i] = __float2half(W[k * 128 + n]);
        } else if (i < 57344) {
            int li = i - 49152;
            int n = li >> 7, k = li & 127;
            wt[i] = __float2half(w2b[k * 64 + n]);
        }
        return;
    }
    copy_range(histBlocks + xcBlocks + tpBlocks, qsrc, qdst, qcount8);
}

// ---------------- build: scan (block 0) + copy (rest) ------------------------
__global__ void scan_copy_kernel(const int* __restrict__ deg, int* __restrict__ rowStart,
                                 int* __restrict__ cursor, int N,
                                 const ulonglong4* __restrict__ qsrc,
                                 ulonglong4* __restrict__ qdst, int qcount8) {
    if (blockIdx.x != 0) { copy_range(1, qsrc, qdst, qcount8); return; }

    __shared__ int warpSums[32];
    __shared__ int running;
    int tid = threadIdx.x, lane = tid & 31, wid = tid >> 5;
    if (tid == 0) running = 0;
    __syncthreads();
    for (int base = 0; base < N; base += 4096) {
        int i0 = base + tid * 4;
        int v0 = 0, v1 = 0, v2 = 0, v3 = 0;
        if (i0 + 3 < N) {
            int4 t = *(const int4*)(deg + i0);
            v0 = t.x; v1 = t.y; v2 = t.z; v3 = t.w;
        } else {
            if (i0 + 0 < N) v0 = deg[i0 + 0];
            if (i0 + 1 < N) v1 = deg[i0 + 1];
            if (i0 + 2 < N) v2 = deg[i0 + 2];
            if (i0 + 3 < N) v3 = deg[i0 + 3];
        }
        int s = v0 + v1 + v2 + v3;
        int val = s;
#pragma unroll
        for (int off = 1; off < 32; off <<= 1) {
            int t = __shfl_up_sync(0xffffffffu, val, off);
            if (lane >= off) val += t;
        }
        if (lane == 31) warpSums[wid] = val;
        __syncthreads();
        if (wid == 0) {
            int w = warpSums[lane];
#pragma unroll
            for (int off = 1; off < 32; off <<= 1) {
                int t = __shfl_up_sync(0xffffffffu, w, off);
                if (lane >= off) w += t;
            }
            warpSums[lane] = w;
        }
        __syncthreads();
        int excl = running + ((wid == 0) ? 0 : warpSums[wid - 1]) + val - s;
        int r = excl;
        if (i0 + 0 < N) { rowStart[i0 + 0] = r; cursor[i0 + 0] = r; r += v0; }
        if (i0 + 1 < N) { rowStart[i0 + 1] = r; cursor[i0 + 1] = r; r += v1; }
        if (i0 + 2 < N) { rowStart[i0 + 2] = r; cursor[i0 + 2] = r; r += v2; }
        if (i0 + 3 < N) { rowStart[i0 + 3] = r; cursor[i0 + 3] = r; r += v3; }
        __syncthreads();
        if (tid == 0) running += warpSums[31];
        __syncthreads();
    }
    if (tid == 0) rowStart[N] = running;
}

// ---------------- build: fill + copy -----------------------------------------
__global__ void fill_copy_kernel(const int* __restrict__ src, const int* __restrict__ dst,
                                 int* __restrict__ cursor, int* __restrict__ adj, int E,
                                 int fillBlocks,
                                 const ulonglong4* __restrict__ qsrc,
                                 ulonglong4* __restrict__ qdst, int qcount8) {
    if ((int)blockIdx.x >= fillBlocks) { copy_range(fillBlocks, qsrc, qdst, qcount8); return; }
    int e = blockIdx.x * blockDim.x + threadIdx.x;
    if (e < E) {
        int p = atomicAdd(&cursor[dst[e]], 1);
        adj[p] = src[e];
    }
}

// ---------------- CSR gather: fp16 in, fp32 accum, fp16 out ------------------
__global__ void gather_kernel(const uint2* __restrict__ h16,
                              const int* __restrict__ rowStart,
                              const int* __restrict__ adj,
                              uint2* __restrict__ out16, int N) {
    int warp = (blockIdx.x * blockDim.x + threadIdx.x) >> 5;
    int lane = threadIdx.x & 31;
    if (warp >= N) return;
    int s = __ldg(rowStart + warp);
    int e = __ldg(rowStart + warp + 1);
    float4 acc = make_float4(0.f, 0.f, 0.f, 0.f);
    acc_h2(acc, __ldg(h16 + (size_t)warp * 32 + lane));   // self term
    int j = s;
    for (; j + 7 < e; j += 8) {
        int idx[8];
#pragma unroll
        for (int q = 0; q < 8; q++) idx[q] = __ldg(adj + j + q);
        uint2 v[8];
#pragma unroll
        for (int q = 0; q < 8; q++) v[q] = __ldg(h16 + (size_t)idx[q] * 32 + lane);
#pragma unroll
        for (int q = 0; q < 8; q++) acc_h2(acc, v[q]);
    }
    for (; j + 3 < e; j += 4) {
        int i0 = __ldg(adj + j),     i1 = __ldg(adj + j + 1);
        int i2 = __ldg(adj + j + 2), i3 = __ldg(adj + j + 3);
        uint2 v0 = __ldg(h16 + (size_t)i0 * 32 + lane);
        uint2 v1 = __ldg(h16 + (size_t)i1 * 32 + lane);
        uint2 v2 = __ldg(h16 + (size_t)i2 * 32 + lane);
        uint2 v3 = __ldg(h16 + (size_t)i3 * 32 + lane);
        acc_h2(acc, v0); acc_h2(acc, v1); acc_h2(acc, v2); acc_h2(acc, v3);
    }
    for (; j < e; j++)
        acc_h2(acc, __ldg(h16 + (size_t)__ldg(adj + j) * 32 + lane));
    __half2 ha = __floats2half2_rn(acc.x, acc.y);
    __half2 hb = __floats2half2_rn(acc.z, acc.w);
    uint2 o;
    o.x = *(uint32_t*)&ha;
    o.y = *(uint32_t*)&hb;
    out16[(size_t)warp * 32 + lane] = o;
}

// ---------------- fp16 MMA tile loop (256 rows x cols, 16 warps) -------------
// A, W in smem as half2 words, rows of 64 data words + 4 pad (WPR=68).
template <int NT>
__device__ __forceinline__ void mma_block16(const uint32_t* __restrict__ sAu,
                                            const uint32_t* __restrict__ sWu,
                                            int arow, int bcol0, float (&d)[2][NT][4]) {
#pragma unroll
    for (int mt = 0; mt < 2; mt++)
#pragma unroll
        for (int nt = 0; nt < NT; nt++)
#pragma unroll
            for (int j = 0; j < 4; j++) d[mt][nt][j] = 0.f;

#pragma unroll
    for (int kt = 0; kt < 8; kt++) {                       // K = 8 x 16
        const int k0 = kt * 8 + (threadIdx.x & 3);
        uint32_t a[2][4];
#pragma unroll
        for (int mt = 0; mt < 2; mt++) {
            int r = arow + mt * 16;
            a[mt][0] = sAu[r * WPR + k0];
            a[mt][1] = sAu[(r + 8) * WPR + k0];
            a[mt][2] = sAu[r * WPR + k0 + 4];
            a[mt][3] = sAu[(r + 8) * WPR + k0 + 4];
        }
#pragma unroll
        for (int nt = 0; nt < NT; nt++) {
            int n = bcol0 + nt * 8 + ((threadIdx.x & 31) >> 2);
            uint32_t b0 = sWu[n * WPR + k0];
            uint32_t b1 = sWu[n * WPR + k0 + 4];
#pragma unroll
            for (int mt = 0; mt < 2; mt++)
                mma_f16(d[mt][nt], a[mt], b0, b1);
        }
    }
}

// ---------------- fused 2-layer MLP (fp16 in, + tail copy blocks) ------------
// OUT_HALF: store result as fp16 rows of 128 halves (layer-1 h output).
template <int M2, int ACT2, int OUT_HALF>
__global__ __launch_bounds__(512, 1)
void mlp_fused(const uint4* __restrict__ A16,
               const uint4* __restrict__ Wt1, const float* __restrict__ b1,
               const uint4* __restrict__ Wt2, const float* __restrict__ b2,
               void* __restrict__ CoutV, int N, int mlpBlocks,
               const ulonglong4* __restrict__ qsrc, ulonglong4* __restrict__ qdst, int qcount8)
{
    constexpr int NT1 = 8;        // 128 / 16
    constexpr int NT2 = M2 / 16;  // 8 or 4

    if ((int)blockIdx.x >= mlpBlocks) { copy_range(mlpBlocks, qsrc, qdst, qcount8); return; }

    extern __shared__ uint32_t smemw[];
    uint32_t* sA  = smemw;                    // [256][WPR] half2 words
    uint32_t* sW  = smemw + 256 * WPR;        // [128][WPR]
    float* sB1 = (float*)(smemw + 256 * WPR + 128 * WPR);
    float* sB2 = sB1 + 128;

    const int tid  = threadIdx.x;
    const int row0 = blockIdx.x * 256;

    // stage W1 (fp16, [n][128])
    for (int i = tid; i < 128 * 16; i += 512) {
        int n = i >> 4, c = i & 15;
        *(uint4*)(sW + n * WPR + c * 4) = Wt1[i];
    }
    if (tid < 128) sB1[tid] = b1[tid];
    if (tid < M2)  sB2[tid] = b2[tid];

    // stage A tile (fp16, [r][128] = 16 uint4 per row)
    for (int i = tid; i < 256 * 16; i += 512) {
        int r = i >> 4, c = i & 15;
        uint4 v = make_uint4(0u, 0u, 0u, 0u);
        if (row0 + r < N) v = A16[(size_t)(row0 + r) * 16 + c];
        *(uint4*)(sA + r * WPR + c * 4) = v;
    }
    __syncthreads();

    const int wid    = tid >> 5;
    const int lane   = tid & 31;
    const int warp_n = wid >> 3;
    const int warp_m = wid & 7;
    const int gid    = lane >> 2;
    const int tig    = lane & 3;
    const int arow   = warp_m * 32 + gid;

    // GEMM1 + bias + relu -> fp16 (kept in registers as fp32 until write)
    float d1[2][NT1][4];
    mma_block16<NT1>(sA, sW, arow, warp_n * 64, d1);
    __syncthreads();   // all GEMM1 smem reads complete

    // intermediate (relu, fp16) -> sA ; W2 -> sW
#pragma unroll
    for (int mt = 0; mt < 2; mt++) {
        int rb = warp_m * 32 + mt * 16 + gid;
#pragma unroll
        for (int half = 0; half < 2; half++) {
            int r = rb + half * 8;
#pragma unroll
            for (int nt = 0; nt < NT1; nt++) {
                int col = warp_n * 64 + nt * 8 + tig * 2;
                float v0 = fmaxf(d1[mt][nt][half * 2 + 0] + sB1[col], 0.f);
                float v1 = fmaxf(d1[mt][nt][half * 2 + 1] + sB1[col + 1], 0.f);
                __half2 hv = __floats2half2_rn(v0, v1);
                sA[r * WPR + (col >> 1)] = *(uint32_t*)&hv;
            }
        }
    }
    for (int i = tid; i < M2 * 16; i += 512) {
        int n = i >> 4, c = i & 15;
        *(uint4*)(sW + n * WPR + c * 4) = Wt2[i];
    }
    __syncthreads();

    // GEMM2 + bias + act2 -> global
    float d2[2][NT2][4];
    mma_block16<NT2>(sA, sW, arow, warp_n * (M2 / 2), d2);
#pragma unroll
    for (int mt = 0; mt < 2; mt++) {
        int rbase = row0 + warp_m * 32 + mt * 16 + gid;
#pragma unroll
        for (int half = 0; half < 2; half++) {
            int r = rbase + half * 8;
            if (r < N) {
#pragma unroll
                for (int nt = 0; nt < NT2; nt++) {
                    int col = warp_n * (M2 / 2) + nt * 8 + tig * 2;
                    float v0 = d2[mt][nt][half * 2 + 0] + sB2[col];
                    float v1 = d2[mt][nt][half * 2 + 1] + sB2[col + 1];
                    if (ACT2 == 2) {
                        v0 = (v0 > 0.f) ? v0 : expm1f(v0);
                        v1 = (v1 > 0.f) ? v1 : expm1f(v1);
                    }
                    if (OUT_HALF) {
                        __half2 hv = __floats2half2_rn(v0, v1);
                        *(uint32_t*)((__half*)CoutV + (size_t)r * M2 + col) = *(uint32_t*)&hv;
                    } else {
                        *(float2*)((float*)CoutV + (size_t)r * M2 + col) = make_float2(v0, v1);
                    }
                }
            }
        }
    }
}

// ---------------------------------------------------------------------------
extern "C" void kernel_launch(void* const* d_in, const int* in_sizes, int n_in,
                              void* d_out, int out_size) {
    const float* x   = (const float*)d_in[0];
    const float* Q   = (const float*)d_in[1];
    const float* w1a = (const float*)d_in[2];
    const float* b1a = (const float*)d_in[3];
    const float* w1b = (const float*)d_in[4];
    const float* b1b = (const float*)d_in[5];
    const float* w2a = (const float*)d_in[6];
    const float* b2a = (const float*)d_in[7];
    const float* w2b = (const float*)d_in[8];
    const float* b2b = (const float*)d_in[9];
    const int*   ei  = (const int*)d_in[10];

    int N = in_sizes[0] / 128;
    int E = in_sizes[10] / 2;
    int C = in_sizes[9];
    int qn = in_sizes[1];

    float* out = (float*)d_out;
    float *buf0, *buf1;
    __half* wt;
    uint2* h16;
    int *adj, *rowStart, *cursor, *deg;
    cudaGetSymbolAddress((void**)&buf0, g_buf0);
    cudaGetSymbolAddress((void**)&buf1, g_buf1);
    cudaGetSymbolAddress((void**)&h16,  g_h16);
    cudaGetSymbolAddress((void**)&wt,   g_wt);
    cudaGetSymbolAddress((void**)&adj,      g_adj);
    cudaGetSymbolAddress((void**)&rowStart, g_rowStart);
    cudaGetSymbolAddress((void**)&cursor,   g_cursor);
    cudaGetSymbolAddress((void**)&deg,      g_deg);

    __half* wt1a = wt;
    __half* wt1b = wt + 16384;
    __half* wt2a = wt + 32768;
    __half* wt2b = wt + 49152;

    uint2* agg1 = (uint2*)buf0;   // fp16 agg buffers (reuse fp32 scratch)
    uint2* agg2 = (uint2*)buf1;

    const int* srcI = ei;
    const int* dstI = ei + E;

    const int smemL = (256 * WPR + 128 * WPR) * 4 + 256 * 4 + 128 * 4;  // ~105 KB
    cudaFuncSetAttribute((const void*)mlp_fused<128, 2, 1>, cudaFuncAttributeMaxDynamicSharedMemorySize, smemL);
    cudaFuncSetAttribute((const void*)mlp_fused<64, 0, 0>,  cudaFuncAttributeMaxDynamicSharedMemorySize, smemL);

    // ---- Q copy split (32B units): build 62%, MLPs 38% ----
    int q8total = qn / 8;
    int qA = (q8total * 22) / 100;
    int qB = (q8total * 20) / 100;
    int qC = (q8total * 20) / 100;
    int qM1 = (q8total * 19) / 100;
    int qM2 = q8total - qA - qB - qC - qM1;
    const ulonglong4* qs = (const ulonglong4*)Q;
    ulonglong4* qd = (ulonglong4*)(out + (size_t)N * C);

    int n32        = N * 32;
    int histBlocks = (E + 255) / 256;
    int xcBlocks   = (n32 + 255) / 256;
    int tpBlocks   = 224;
    int fillBlocks = (E + 255) / 256;
    int gatBlocks  = (N * 32 + 255) / 256;
    int copyBlocks = 1600;
    int mlpBlocks  = (N + 255) / 256;
    int mlpCopyBlocks = 120;

    long o = 0;

    // ---- CSR build (+ x->fp16 + transpose + copy folded in) ----
    cudaMemsetAsync(deg, 0, N * sizeof(int), 0);
    hist_xc_tp_copy_kernel<<<histBlocks + xcBlocks + tpBlocks + copyBlocks, 256>>>(
        dstI, deg, E, histBlocks,
        (const float4*)x, h16, n32, xcBlocks,
        w1a, w1b, w2a, w2b, wt, tpBlocks,
        qs + o, qd + o, qA);
    o += qA;
    scan_copy_kernel<<<1 + copyBlocks, 1024>>>(deg, rowStart, cursor, N, qs + o, qd + o, qB);
    o += qB;
    fill_copy_kernel<<<fillBlocks + copyBlocks, 256>>>(
        srcI, dstI, cursor, adj, E, fillBlocks, qs + o, qd + o, qC);
    o += qC;

    // ---- layer 1: gather x16 -> agg1 (fp16); mlp -> h16 (fp16) ----
    gather_kernel<<<gatBlocks, 256>>>(h16, rowStart, adj, agg1, N);
    mlp_fused<128, 2, 1><<<mlpBlocks + mlpCopyBlocks, 512, smemL>>>(
        (const uint4*)agg1, (const uint4*)wt1a, b1a, (const uint4*)wt1b, b1b,
        (void*)h16, N, mlpBlocks, qs + o, qd + o, qM1);
    o += qM1;

    // ---- layer 2: gather h16 -> agg2 (fp16); mlp -> out (fp32) ----
    gather_kernel<<<gatBlocks, 256>>>(h16, rowStart, adj, agg2, N);
    mlp_fused<64, 0, 0><<<mlpBlocks + mlpCopyBlocks, 512, smemL>>>(
        (const uint4*)agg2, (const uint4*)wt2a, b2a, (const uint4*)wt2b, b2b,
        (void*)out, N, mlpBlocks, qs + o, qd + o, qM2);
}